// round 9
// baseline (speedup 1.0000x reference)
#include <cuda_runtime.h>
#include <cuda_fp16.h>
#include <math.h>
#include <stdint.h>

// Problem constants
#define DIMM 5120
#define NHEADS 40
#define HDIM 128
#define BB 2
#define LL 1024
#define TOKENS (BB*LL)          // 2048
#define QKVDIM (3*DIMM)         // 15360
#define SCALE 0.08838834764831845f
#define EPS 1e-6f

// -------- scratch (static device globals; no runtime allocation) --------
__device__ float  g_qkv[(size_t)TOKENS * QKVDIM];           // 125.8 MB f32
__device__ __half g_q[(size_t)TOKENS * DIMM];               // scaled by SCALE
__device__ __half g_k[(size_t)TOKENS * DIMM];
__device__ __half g_o[(size_t)TOKENS * DIMM];
__device__ __half g_vt[(size_t)BB * NHEADS * HDIM * LL];    // V^T per head
__device__ __half g_wq[(size_t)QKVDIM * DIMM];              // W_qkv^T [N,K]
__device__ __half g_wo[(size_t)DIMM * DIMM];                // W_out^T [N,K]
__device__ __half g_x[(size_t)TOKENS * DIMM];               // x, half

// ============================================================
// helpers
// ============================================================
__device__ __forceinline__ uint32_t smem_u32(const void* p) {
    uint32_t a;
    asm("{ .reg .u64 t; cvta.to.shared.u64 t, %1; cvt.u32.u64 %0, t; }" : "=r"(a) : "l"(p));
    return a;
}
__device__ __forceinline__ void cpa16(uint32_t dst, const void* src) {
    asm volatile("cp.async.cg.shared.global [%0], [%1], 16;" :: "r"(dst), "l"(src));
}
#define CPA_COMMIT() asm volatile("cp.async.commit_group;" ::: "memory")
#define CPA_WAIT1()  asm volatile("cp.async.wait_group 1;" ::: "memory")
#define CPA_WAIT0()  asm volatile("cp.async.wait_group 0;" ::: "memory")

// fp16 m16n8k16, f32 accum
__device__ __forceinline__ void mma16816(float* d, const uint32_t* a, uint32_t b0, uint32_t b1) {
    asm volatile(
        "mma.sync.aligned.m16n8k16.row.col.f32.f16.f16.f32 "
        "{%0,%1,%2,%3}, {%4,%5,%6,%7}, {%8,%9}, {%0,%1,%2,%3};"
        : "+f"(d[0]), "+f"(d[1]), "+f"(d[2]), "+f"(d[3])
        : "r"(a[0]), "r"(a[1]), "r"(a[2]), "r"(a[3]), "r"(b0), "r"(b1));
}
__device__ __forceinline__ void ldsm4(uint32_t* r, uint32_t addr) {
    asm volatile("ldmatrix.sync.aligned.m8n8.x4.shared.b16 {%0,%1,%2,%3}, [%4];"
        : "=r"(r[0]), "=r"(r[1]), "=r"(r[2]), "=r"(r[3]) : "r"(addr));
}
__device__ __forceinline__ uint32_t packh2(float x, float y) {
    __half2 h = __floats2half2_rn(x, y);
    return *(uint32_t*)&h;
}

// ============================================================
// fp16 mma.sync GEMM, crossbar-balanced tiling:
//   C[z][m,n] = alpha * A[z][m,:K] * Bt[z][n,:K]^T (+ bias[n])
// CTA tile 256x128, 8 warps in 4(M) x 2(N), warp tile 64x64.
// K-chunk 64, 3-stage cp.async, 1 CTA/SM (166KB smem, ~180 regs).
// Per k16 step/warp: 8 ldsm feed 32 MMA -> smem crossbar == tensor pipe.
// ============================================================
#define KC 64
#define ROWB 144
#define A_TILE_B (256 * ROWB)               // 36864
#define B_TILE_B (128 * ROWB)               // 18432
#define STAGE_B (A_TILE_B + B_TILE_B)       // 55296
#define NSTG 3
#define GEMM_SMEM (NSTG * STAGE_B)          // 165888 B

__global__ __launch_bounds__(256, 1) void tc_gemm(
    const __half* __restrict__ A, const __half* __restrict__ Bt,
    const float* __restrict__ bias, void* __restrict__ Cv,
    long sAz, long sBz, long sCz,
    int lda, int ldb, int ldc, int K, float alpha, int store_half)
{
    extern __shared__ char sm[];
    const uint32_t sb = smem_u32(sm);

    A  += (size_t)blockIdx.z * sAz;
    Bt += (size_t)blockIdx.z * sBz;

    const int tid  = threadIdx.x;
    const int warp = tid >> 5;
    const int lane = tid & 31;
    const int wm = warp >> 1;          // 0..3  (64-row slice of 256)
    const int wn = warp & 1;           // 0..1  (64-col slice of 128)
    const int m0 = blockIdx.x * 256;
    const int n0 = blockIdx.y * 128;

    const uint32_t aOff = (uint32_t)(lane & 15) * ROWB + (uint32_t)(lane >> 4) * 16;
    const uint32_t bOff = (uint32_t)((lane & 7) + ((lane >> 4) & 1) * 8) * ROWB
                        + (uint32_t)((lane >> 3) & 1) * 16;

    float acc[4][8][4];
#pragma unroll
    for (int mt = 0; mt < 4; mt++)
#pragma unroll
        for (int nt = 0; nt < 8; nt++)
#pragma unroll
            for (int r = 0; r < 4; r++) acc[mt][nt][r] = 0.f;

    const int nch = K / KC;

    auto load_chunk = [&](int st, int kc) {
        uint32_t base = sb + (uint32_t)st * STAGE_B;
        // A: 256 rows x 8 granules = 2048; 8 per thread
#pragma unroll
        for (int i = 0; i < 8; i++) {
            int op = tid + i * 256;
            int row = op >> 3, g = op & 7;
            cpa16(base + (uint32_t)row * ROWB + (uint32_t)g * 16,
                  (const char*)A + ((size_t)(m0 + row) * lda + kc + g * 8) * 2);
        }
        // B: 128 rows x 8 granules = 1024; 4 per thread
#pragma unroll
        for (int i = 0; i < 4; i++) {
            int op = tid + i * 256;
            int row = op >> 3, g = op & 7;
            cpa16(base + A_TILE_B + (uint32_t)row * ROWB + (uint32_t)g * 16,
                  (const char*)Bt + ((size_t)(n0 + row) * ldb + kc + g * 8) * 2);
        }
    };

    load_chunk(0, 0);       CPA_COMMIT();
    if (nch > 1) { load_chunk(1, KC); CPA_COMMIT(); }

    for (int c = 0; c < nch; c++) {
        const int st = c % NSTG;
        if (c + 1 < nch) { CPA_WAIT1(); } else { CPA_WAIT0(); }
        __syncthreads();
        if (c + 2 < nch) { load_chunk((c + 2) % NSTG, (c + 2) * KC); CPA_COMMIT(); }

        const uint32_t aBase = sb + (uint32_t)st * STAGE_B
                             + (uint32_t)(wm * 64) * ROWB + aOff;
        const uint32_t bBase = sb + (uint32_t)st * STAGE_B + A_TILE_B
                             + (uint32_t)(wn * 64) * ROWB + bOff;

#pragma unroll
        for (int s = 0; s < 4; s++) {
            const uint32_t kb = (uint32_t)s * 32;
            uint32_t af[4][4];
#pragma unroll
            for (int mt = 0; mt < 4; mt++)
                ldsm4(af[mt], aBase + (uint32_t)(mt * 16) * ROWB + kb);
            uint32_t bf[4][4];
#pragma unroll
            for (int np = 0; np < 4; np++)
                ldsm4(bf[np], bBase + (uint32_t)(np * 16) * ROWB + kb);
#pragma unroll
            for (int mt = 0; mt < 4; mt++)
#pragma unroll
                for (int nt = 0; nt < 8; nt++)
                    mma16816(acc[mt][nt], af[mt],
                             bf[nt >> 1][(nt & 1) * 2], bf[nt >> 1][(nt & 1) * 2 + 1]);
        }
    }

    // epilogue: warp writes its 64x64 region
    {
        const int r = lane >> 2, cq = lane & 3;
#pragma unroll
        for (int mt = 0; mt < 4; mt++) {
            int row = m0 + wm * 64 + mt * 16 + r;
#pragma unroll
            for (int nt = 0; nt < 8; nt++) {
                int col = n0 + wn * 64 + nt * 8 + 2 * cq;
                float bvx = 0.f, bvy = 0.f;
                if (bias) { float2 bv = *(const float2*)(bias + col); bvx = bv.x; bvy = bv.y; }
                float o0x = fmaf(acc[mt][nt][0], alpha, bvx);
                float o0y = fmaf(acc[mt][nt][1], alpha, bvy);
                float o1x = fmaf(acc[mt][nt][2], alpha, bvx);
                float o1y = fmaf(acc[mt][nt][3], alpha, bvy);
                if (store_half) {
                    __half* C = (__half*)Cv + (size_t)blockIdx.z * sCz;
                    *(__half2*)(C + (size_t)row * ldc + col) = __floats2half2_rn(o0x, o0y);
                    *(__half2*)(C + (size_t)(row + 8) * ldc + col) = __floats2half2_rn(o1x, o1y);
                } else {
                    float* C = (float*)Cv + (size_t)blockIdx.z * sCz;
                    *(float2*)(C + (size_t)row * ldc + col) = make_float2(o0x, o0y);
                    *(float2*)(C + (size_t)(row + 8) * ldc + col) = make_float2(o1x, o1y);
                }
            }
        }
    }
}

// ============================================================
// Flash attention (unchanged from R8): CTA = 128 q rows x one (b,h).
// ============================================================
#define FROWB 272
#define FTILE_B (128 * FROWB)               // 34816
#define FLASH_SMEM (5 * FTILE_B)            // 174080: Q + 2x(K+V)

__global__ __launch_bounds__(256, 1) void flash_kernel()
{
    extern __shared__ char sm[];
    const uint32_t sb = smem_u32(sm);
    const int tid = threadIdx.x, warp = tid >> 5, lane = tid & 31;
    const int bh = blockIdx.y;
    const int b = bh / NHEADS, h = bh % NHEADS;
    const int q0 = blockIdx.x * 128;

    const char* Qg = (const char*)(g_q + ((size_t)(b * LL + q0)) * DIMM + h * HDIM);
    const char* Kg = (const char*)(g_k + ((size_t)(b * LL)) * DIMM + h * HDIM);
    const char* Vg = (const char*)(g_vt + (size_t)bh * HDIM * LL);

    const uint32_t aOff = (uint32_t)(lane & 15) * FROWB + (uint32_t)(lane >> 4) * 16;
    const uint32_t bOff = (uint32_t)((lane & 7) + ((lane >> 4) & 1) * 8) * FROWB
                        + (uint32_t)((lane >> 3) & 1) * 16;

    auto load_kv = [&](int st, int j) {
        uint32_t kb = sb + FTILE_B + (uint32_t)st * (2 * FTILE_B);
        uint32_t vb = kb + FTILE_B;
#pragma unroll
        for (int i = 0; i < 8; i++) {
            int op = tid + i * 256;
            int row = op >> 4, g = op & 15;
            uint32_t off = (uint32_t)row * FROWB + (uint32_t)g * 16;
            cpa16(kb + off, Kg + ((size_t)(j * 128 + row) * DIMM) * 2 + g * 16);
            cpa16(vb + off, Vg + ((size_t)row * LL + j * 128) * 2 + g * 16);
        }
    };

    {
#pragma unroll
        for (int i = 0; i < 8; i++) {
            int op = tid + i * 256;
            int row = op >> 4, g = op & 15;
            cpa16(sb + (uint32_t)row * FROWB + (uint32_t)g * 16,
                  Qg + (size_t)row * DIMM * 2 + g * 16);
        }
        CPA_COMMIT();
        load_kv(0, 0); CPA_COMMIT();
        CPA_WAIT1();
        __syncthreads();
    }

    uint32_t aq[8][4];
    {
        uint32_t qBase = sb + (uint32_t)(warp * 16) * FROWB + aOff;
#pragma unroll
        for (int kk = 0; kk < 8; kk++)
            ldsm4(aq[kk], qBase + (uint32_t)kk * 32);
    }

    float accO[16][4];
#pragma unroll
    for (int nt = 0; nt < 16; nt++)
#pragma unroll
        for (int r = 0; r < 4; r++) accO[nt][r] = 0.f;
    float m0 = -1e30f, m1 = -1e30f, l0 = 0.f, l1 = 0.f;

    for (int j = 0; j < 8; j++) {
        const int st = j & 1;
        CPA_WAIT0();
        __syncthreads();
        if (j + 1 < 8) { load_kv((j + 1) & 1, j + 1); CPA_COMMIT(); }

        const uint32_t kBase = sb + FTILE_B + (uint32_t)st * (2 * FTILE_B) + bOff;
        const uint32_t vBase = kBase + FTILE_B;

        float sA[16][4];
#pragma unroll
        for (int nt = 0; nt < 16; nt++)
#pragma unroll
            for (int r = 0; r < 4; r++) sA[nt][r] = 0.f;
#pragma unroll
        for (int kk = 0; kk < 8; kk++) {
#pragma unroll
            for (int np = 0; np < 8; np++) {
                uint32_t bf[4];
                ldsm4(bf, kBase + (uint32_t)(np * 16) * FROWB + (uint32_t)kk * 32);
                mma16816(sA[2 * np],     aq[kk], bf[0], bf[1]);
                mma16816(sA[2 * np + 1], aq[kk], bf[2], bf[3]);
            }
        }

        float mx0 = -1e30f, mx1 = -1e30f;
#pragma unroll
        for (int nt = 0; nt < 16; nt++) {
            mx0 = fmaxf(mx0, fmaxf(sA[nt][0], sA[nt][1]));
            mx1 = fmaxf(mx1, fmaxf(sA[nt][2], sA[nt][3]));
        }
        mx0 = fmaxf(mx0, __shfl_xor_sync(0xffffffffu, mx0, 1));
        mx0 = fmaxf(mx0, __shfl_xor_sync(0xffffffffu, mx0, 2));
        mx1 = fmaxf(mx1, __shfl_xor_sync(0xffffffffu, mx1, 1));
        mx1 = fmaxf(mx1, __shfl_xor_sync(0xffffffffu, mx1, 2));
        float mn0 = fmaxf(m0, mx0), mn1 = fmaxf(m1, mx1);
        float c0 = __expf(m0 - mn0), c1 = __expf(m1 - mn1);
        l0 *= c0; l1 *= c1;
#pragma unroll
        for (int nt = 0; nt < 16; nt++) {
            accO[nt][0] *= c0; accO[nt][1] *= c0;
            accO[nt][2] *= c1; accO[nt][3] *= c1;
        }
        float s0 = 0.f, s1 = 0.f;
        uint32_t pa0[16], pa1[16];
#pragma unroll
        for (int nt = 0; nt < 16; nt++) {
            float p0 = __expf(sA[nt][0] - mn0);
            float p1 = __expf(sA[nt][1] - mn0);
            float p2 = __expf(sA[nt][2] - mn1);
            float p3 = __expf(sA[nt][3] - mn1);
            s0 += p0 + p1; s1 += p2 + p3;
            pa0[nt] = packh2(p0, p1);
            pa1[nt] = packh2(p2, p3);
        }
        s0 += __shfl_xor_sync(0xffffffffu, s0, 1);
        s0 += __shfl_xor_sync(0xffffffffu, s0, 2);
        s1 += __shfl_xor_sync(0xffffffffu, s1, 1);
        s1 += __shfl_xor_sync(0xffffffffu, s1, 2);
        l0 += s0; l1 += s1; m0 = mn0; m1 = mn1;

#pragma unroll
        for (int kk = 0; kk < 8; kk++) {
            uint32_t a[4] = { pa0[2 * kk], pa1[2 * kk], pa0[2 * kk + 1], pa1[2 * kk + 1] };
#pragma unroll
            for (int np = 0; np < 8; np++) {
                uint32_t bf[4];
                ldsm4(bf, vBase + (uint32_t)(np * 16) * FROWB + (uint32_t)kk * 32);
                mma16816(accO[2 * np],     a, bf[0], bf[1]);
                mma16816(accO[2 * np + 1], a, bf[2], bf[3]);
            }
        }
    }

    {
        float i0 = 1.f / l0, i1 = 1.f / l1;
        const int r = lane >> 2, cq = lane & 3;
        __half* Og = g_o + ((size_t)(b * LL + q0 + warp * 16)) * DIMM + h * HDIM;
#pragma unroll
        for (int nt = 0; nt < 16; nt++) {
            int col = nt * 8 + 2 * cq;
            *(__half2*)(Og + (size_t)r * DIMM + col) =
                __floats2half2_rn(accO[nt][0] * i0, accO[nt][1] * i0);
            *(__half2*)(Og + (size_t)(r + 8) * DIMM + col) =
                __floats2half2_rn(accO[nt][2] * i1, accO[nt][3] * i1);
        }
    }
}

// ============================================================
// convert helpers
// ============================================================
__global__ void cvt_h_kernel(const float* __restrict__ s, __half* __restrict__ d, size_t n4)
{
    size_t i = (size_t)blockIdx.x * blockDim.x + threadIdx.x;
    if (i < n4) {
        float4 v = ((const float4*)s)[i];
        ((__half2*)d)[2 * i]     = __floats2half2_rn(v.x, v.y);
        ((__half2*)d)[2 * i + 1] = __floats2half2_rn(v.z, v.w);
    }
}

__global__ void cvtT_kernel(const float* __restrict__ src, __half* __restrict__ dst,
                            int K, int N)
{
    __shared__ float tile[32][33];
    int k0 = blockIdx.y * 32, n0 = blockIdx.x * 32;
    int tx = threadIdx.x, ty = threadIdx.y;
#pragma unroll
    for (int i = 0; i < 32; i += 8)
        tile[ty + i][tx] = src[(size_t)(k0 + ty + i) * N + n0 + tx];
    __syncthreads();
#pragma unroll
    for (int i = 0; i < 32; i += 8)
        dst[(size_t)(n0 + ty + i) * K + k0 + tx] = __float2half_rn(tile[tx][ty + i]);
}

// V^T per head
__global__ void vtrans_kernel()
{
    __shared__ float tile[32][33];
    const int bh = blockIdx.z;
    const int b = bh / NHEADS, h = bh % NHEADS;
    const int k0 = blockIdx.x * 32, d0 = blockIdx.y * 32;
    const float* src = g_qkv + (size_t)b * LL * QKVDIM + 2 * DIMM + h * HDIM;
    __half* dst = g_vt + (size_t)bh * HDIM * LL;
    int tx = threadIdx.x, ty = threadIdx.y;
#pragma unroll
    for (int i = 0; i < 32; i += 8)
        tile[ty + i][tx] = src[(size_t)(k0 + ty + i) * QKVDIM + d0 + tx];
    __syncthreads();
#pragma unroll
    for (int i = 0; i < 32; i += 8)
        dst[(size_t)(d0 + ty + i) * LL + k0 + tx] = __float2half_rn(tile[tx][ty + i]);
}

// ============================================================
// RMSNorm + gain + RoPE -> half q (pre-scaled by SCALE), k
// ============================================================
__global__ __launch_bounds__(256) void rmsrope_kernel(
    const float* __restrict__ cosb, const float* __restrict__ sinb,
    const float* __restrict__ gq, const float* __restrict__ gk)
{
    const int t = blockIdx.x;
    const int tid = threadIdx.x;
    const float* base = g_qkv + (size_t)t * QKVDIM;

    float sq = 0.f, sk = 0.f;
    for (int i = tid; i < DIMM; i += 256) {
        float a = base[i];         sq = fmaf(a, a, sq);
        float b = base[DIMM + i];  sk = fmaf(b, b, sk);
    }
    __shared__ float r1[256], r2[256];
    r1[tid] = sq; r2[tid] = sk;
    __syncthreads();
    for (int s = 128; s > 0; s >>= 1) {
        if (tid < s) { r1[tid] += r1[tid + s]; r2[tid] += r2[tid + s]; }
        __syncthreads();
    }
    const float rq = rsqrtf(r1[0] / (float)DIMM + EPS);
    const float rk = rsqrtf(r2[0] / (float)DIMM + EPS);

    const int l = t & (LL - 1);
    const float* cl = cosb + (size_t)l * HDIM;
    const float* sl = sinb + (size_t)l * HDIM;
    __half* qo = g_q + (size_t)t * DIMM;
    __half* ko = g_k + (size_t)t * DIMM;

    for (int p = tid; p < DIMM / 2; p += 256) {
        int d = 2 * p;
        int hd = d & (HDIM - 1);
        float c = cl[hd];
        float s = sl[hd + 1];
        float x0 = base[d]     * rq * gq[d];
        float x1 = base[d + 1] * rq * gq[d + 1];
        *(__half2*)(qo + d) = __floats2half2_rn((x0 * c - x1 * s) * SCALE,
                                                (x0 * s + x1 * c) * SCALE);
        float y0 = base[DIMM + d]     * rk * gk[d];
        float y1 = base[DIMM + d + 1] * rk * gk[d + 1];
        *(__half2*)(ko + d) = __floats2half2_rn(y0 * c - y1 * s, y0 * s + y1 * c);
    }
}

// ============================================================
// launch
// ============================================================
extern "C" void kernel_launch(void* const* d_in, const int* in_sizes, int n_in,
                              void* d_out, int out_size)
{
    const float* x     = (const float*)d_in[0];
    const float* cosb  = (const float*)d_in[1];
    const float* sinb  = (const float*)d_in[2];
    const float* Wqkv  = (const float*)d_in[3];
    const float* bqkv  = (const float*)d_in[4];
    const float* gq    = (const float*)d_in[5];
    const float* gk    = (const float*)d_in[6];
    const float* Wout  = (const float*)d_in[7];
    const float* bout  = (const float*)d_in[8];
    float* out = (float*)d_out;

    void* p_qkv; cudaGetSymbolAddress(&p_qkv, g_qkv);
    void* p_o;   cudaGetSymbolAddress(&p_o,   g_o);
    void* p_wq;  cudaGetSymbolAddress(&p_wq,  g_wq);
    void* p_wo;  cudaGetSymbolAddress(&p_wo,  g_wo);
    void* p_x;   cudaGetSymbolAddress(&p_x,   g_x);

    cudaFuncSetAttribute(tc_gemm, cudaFuncAttributeMaxDynamicSharedMemorySize, GEMM_SMEM);
    cudaFuncSetAttribute(flash_kernel, cudaFuncAttributeMaxDynamicSharedMemorySize, FLASH_SMEM);

    // 0) weight transpose + fp16 rounding; activation rounding
    cvtT_kernel<<<dim3(QKVDIM / 32, DIMM / 32), dim3(32, 8)>>>(Wqkv, (__half*)p_wq, DIMM, QKVDIM);
    cvtT_kernel<<<dim3(DIMM / 32,  DIMM / 32), dim3(32, 8)>>>(Wout, (__half*)p_wo, DIMM, DIMM);
    {
        size_t n4 = (size_t)TOKENS * DIMM / 4;
        cvt_h_kernel<<<(unsigned)((n4 + 255) / 256), 256>>>(x, (__half*)p_x, n4);
    }

    // 1) QKV projection (M-tiles of 256)
    tc_gemm<<<dim3(TOKENS / 256, QKVDIM / 128, 1), 256, GEMM_SMEM>>>(
        (const __half*)p_x, (const __half*)p_wq, bqkv, p_qkv,
        0, 0, 0, DIMM, DIMM, QKVDIM, DIMM, 1.f, 0);

    // 2) RMSNorm + RoPE (half out, q pre-scaled), V transpose (half out)
    rmsrope_kernel<<<TOKENS, 256>>>(cosb, sinb, gq, gk);
    vtrans_kernel<<<dim3(LL / 32, HDIM / 32, BB * NHEADS), dim3(32, 8)>>>();

    // 3) fused attention
    flash_kernel<<<dim3(LL / 128, BB * NHEADS), 256, FLASH_SMEM>>>();

    // 4) out projection
    tc_gemm<<<dim3(TOKENS / 256, DIMM / 128, 1), 256, GEMM_SMEM>>>(
        (const __half*)p_o, (const __half*)p_wo, bout, out,
        0, 0, 0, DIMM, DIMM, DIMM, DIMM, 1.f, 0);
}

// round 10
// speedup vs baseline: 1.0550x; 1.0550x over previous
#include <cuda_runtime.h>
#include <cuda_fp16.h>
#include <math.h>
#include <stdint.h>

// Problem constants
#define DIMM 5120
#define NHEADS 40
#define HDIM 128
#define BB 2
#define LL 1024
#define TOKENS (BB*LL)          // 2048
#define QKVDIM (3*DIMM)         // 15360
#define SCALE 0.08838834764831845f
#define EPS 1e-6f

// -------- scratch (static device globals; no runtime allocation) --------
__device__ float  g_qkv[(size_t)TOKENS * QKVDIM];           // 125.8 MB f32
__device__ __half g_q[(size_t)TOKENS * DIMM];               // scaled by SCALE
__device__ __half g_k[(size_t)TOKENS * DIMM];
__device__ __half g_o[(size_t)TOKENS * DIMM];
__device__ __half g_vt[(size_t)BB * NHEADS * HDIM * LL];    // V^T per head
__device__ __half g_wq[(size_t)QKVDIM * DIMM];              // W_qkv^T [N,K]
__device__ __half g_wo[(size_t)DIMM * DIMM];                // W_out^T [N,K]
__device__ __half g_x[(size_t)TOKENS * DIMM];               // x, half

// ============================================================
// helpers
// ============================================================
__device__ __forceinline__ uint32_t smem_u32(const void* p) {
    uint32_t a;
    asm("{ .reg .u64 t; cvta.to.shared.u64 t, %1; cvt.u32.u64 %0, t; }" : "=r"(a) : "l"(p));
    return a;
}
__device__ __forceinline__ void cpa16(uint32_t dst, const void* src) {
    asm volatile("cp.async.cg.shared.global [%0], [%1], 16;" :: "r"(dst), "l"(src));
}
#define CPA_COMMIT() asm volatile("cp.async.commit_group;" ::: "memory")
#define CPA_WAIT1()  asm volatile("cp.async.wait_group 1;" ::: "memory")
#define CPA_WAIT0()  asm volatile("cp.async.wait_group 0;" ::: "memory")

// fp16 m16n8k16, f32 accum
__device__ __forceinline__ void mma16816(float* d, const uint32_t* a, uint32_t b0, uint32_t b1) {
    asm volatile(
        "mma.sync.aligned.m16n8k16.row.col.f32.f16.f16.f32 "
        "{%0,%1,%2,%3}, {%4,%5,%6,%7}, {%8,%9}, {%0,%1,%2,%3};"
        : "+f"(d[0]), "+f"(d[1]), "+f"(d[2]), "+f"(d[3])
        : "r"(a[0]), "r"(a[1]), "r"(a[2]), "r"(a[3]), "r"(b0), "r"(b1));
}
__device__ __forceinline__ void ldsm4(uint32_t* r, uint32_t addr) {
    asm volatile("ldmatrix.sync.aligned.m8n8.x4.shared.b16 {%0,%1,%2,%3}, [%4];"
        : "=r"(r[0]), "=r"(r[1]), "=r"(r[2]), "=r"(r[3]) : "r"(addr));
}
__device__ __forceinline__ uint32_t packh2(float x, float y) {
    __half2 h = __floats2half2_rn(x, y);
    return *(uint32_t*)&h;
}

// ============================================================
// fp16 mma.sync GEMM:
//   C[z][m,n] = alpha * A[z][m,:K] * Bt[z][n,:K]^T (+ bias[n])
// CTA tile 128x128, 128 threads = 4 warps in 2(M) x 2(N), warp tile 64x64.
// K-chunk 64, 3-stage cp.async, 2 CTAs/SM (110.6KB smem, ~226 regs x 128thr).
// Crossbar per SM-chunk: 1536 cyc vs tensor 2048 -> tensor-limited.
// ============================================================
#define KC 64
#define ROWB 144
#define TILE_B (128 * ROWB)                 // 18432
#define STAGE_B (2 * TILE_B)                // 36864 (A + B)
#define NSTG 3
#define GEMM_SMEM (NSTG * STAGE_B)          // 110592 B

__global__ __launch_bounds__(128, 2) void tc_gemm(
    const __half* __restrict__ A, const __half* __restrict__ Bt,
    const float* __restrict__ bias, void* __restrict__ Cv,
    long sAz, long sBz, long sCz,
    int lda, int ldb, int ldc, int K, float alpha, int store_half)
{
    extern __shared__ char sm[];
    const uint32_t sb = smem_u32(sm);

    A  += (size_t)blockIdx.z * sAz;
    Bt += (size_t)blockIdx.z * sBz;

    const int tid  = threadIdx.x;
    const int warp = tid >> 5;
    const int lane = tid & 31;
    const int wm = warp >> 1;          // 0..1 (64-row slice)
    const int wn = warp & 1;           // 0..1 (64-col slice)
    const int m0 = blockIdx.x * 128;
    const int n0 = blockIdx.y * 128;

    const uint32_t aOff = (uint32_t)(lane & 15) * ROWB + (uint32_t)(lane >> 4) * 16;
    const uint32_t bOff = (uint32_t)((lane & 7) + ((lane >> 4) & 1) * 8) * ROWB
                        + (uint32_t)((lane >> 3) & 1) * 16;

    float acc[4][8][4];
#pragma unroll
    for (int mt = 0; mt < 4; mt++)
#pragma unroll
        for (int nt = 0; nt < 8; nt++)
#pragma unroll
            for (int r = 0; r < 4; r++) acc[mt][nt][r] = 0.f;

    const int nch = K / KC;

    auto load_chunk = [&](int st, int kc) {
        uint32_t base = sb + (uint32_t)st * STAGE_B;
        // A: 1024 granules, 8 per thread; B: same
#pragma unroll
        for (int i = 0; i < 8; i++) {
            int op = tid + i * 128;
            int row = op >> 3, g = op & 7;
            uint32_t off = (uint32_t)row * ROWB + (uint32_t)g * 16;
            cpa16(base + off,
                  (const char*)A + ((size_t)(m0 + row) * lda + kc + g * 8) * 2);
            cpa16(base + TILE_B + off,
                  (const char*)Bt + ((size_t)(n0 + row) * ldb + kc + g * 8) * 2);
        }
    };

    load_chunk(0, 0);       CPA_COMMIT();
    if (nch > 1) { load_chunk(1, KC); CPA_COMMIT(); }

    for (int c = 0; c < nch; c++) {
        const int st = c % NSTG;
        if (c + 1 < nch) { CPA_WAIT1(); } else { CPA_WAIT0(); }
        __syncthreads();
        if (c + 2 < nch) { load_chunk((c + 2) % NSTG, (c + 2) * KC); CPA_COMMIT(); }

        const uint32_t aBase = sb + (uint32_t)st * STAGE_B
                             + (uint32_t)(wm * 64) * ROWB + aOff;
        const uint32_t bBase = sb + (uint32_t)st * STAGE_B + TILE_B
                             + (uint32_t)(wn * 64) * ROWB + bOff;

#pragma unroll
        for (int s = 0; s < 4; s++) {
            const uint32_t kb = (uint32_t)s * 32;
            uint32_t af[4][4];
#pragma unroll
            for (int mt = 0; mt < 4; mt++)
                ldsm4(af[mt], aBase + (uint32_t)(mt * 16) * ROWB + kb);
            uint32_t bf[4][4];
#pragma unroll
            for (int np = 0; np < 4; np++)
                ldsm4(bf[np], bBase + (uint32_t)(np * 16) * ROWB + kb);
#pragma unroll
            for (int mt = 0; mt < 4; mt++)
#pragma unroll
                for (int nt = 0; nt < 8; nt++)
                    mma16816(acc[mt][nt], af[mt],
                             bf[nt >> 1][(nt & 1) * 2], bf[nt >> 1][(nt & 1) * 2 + 1]);
        }
    }

    // epilogue: warp writes its 64x64 region
    {
        const int r = lane >> 2, cq = lane & 3;
#pragma unroll
        for (int mt = 0; mt < 4; mt++) {
            int row = m0 + wm * 64 + mt * 16 + r;
#pragma unroll
            for (int nt = 0; nt < 8; nt++) {
                int col = n0 + wn * 64 + nt * 8 + 2 * cq;
                float bvx = 0.f, bvy = 0.f;
                if (bias) { float2 bv = *(const float2*)(bias + col); bvx = bv.x; bvy = bv.y; }
                float o0x = fmaf(acc[mt][nt][0], alpha, bvx);
                float o0y = fmaf(acc[mt][nt][1], alpha, bvy);
                float o1x = fmaf(acc[mt][nt][2], alpha, bvx);
                float o1y = fmaf(acc[mt][nt][3], alpha, bvy);
                if (store_half) {
                    __half* C = (__half*)Cv + (size_t)blockIdx.z * sCz;
                    *(__half2*)(C + (size_t)row * ldc + col) = __floats2half2_rn(o0x, o0y);
                    *(__half2*)(C + (size_t)(row + 8) * ldc + col) = __floats2half2_rn(o1x, o1y);
                } else {
                    float* C = (float*)Cv + (size_t)blockIdx.z * sCz;
                    *(float2*)(C + (size_t)row * ldc + col) = make_float2(o0x, o0y);
                    *(float2*)(C + (size_t)(row + 8) * ldc + col) = make_float2(o1x, o1y);
                }
            }
        }
    }
}

// ============================================================
// Flash attention (R8 version): CTA = 128 q rows x one (b,h).
// ============================================================
#define FROWB 272
#define FTILE_B (128 * FROWB)               // 34816
#define FLASH_SMEM (5 * FTILE_B)            // 174080: Q + 2x(K+V)

__global__ __launch_bounds__(256, 1) void flash_kernel()
{
    extern __shared__ char sm[];
    const uint32_t sb = smem_u32(sm);
    const int tid = threadIdx.x, warp = tid >> 5, lane = tid & 31;
    const int bh = blockIdx.y;
    const int b = bh / NHEADS, h = bh % NHEADS;
    const int q0 = blockIdx.x * 128;

    const char* Qg = (const char*)(g_q + ((size_t)(b * LL + q0)) * DIMM + h * HDIM);
    const char* Kg = (const char*)(g_k + ((size_t)(b * LL)) * DIMM + h * HDIM);
    const char* Vg = (const char*)(g_vt + (size_t)bh * HDIM * LL);

    const uint32_t aOff = (uint32_t)(lane & 15) * FROWB + (uint32_t)(lane >> 4) * 16;
    const uint32_t bOff = (uint32_t)((lane & 7) + ((lane >> 4) & 1) * 8) * FROWB
                        + (uint32_t)((lane >> 3) & 1) * 16;

    auto load_kv = [&](int st, int j) {
        uint32_t kb = sb + FTILE_B + (uint32_t)st * (2 * FTILE_B);
        uint32_t vb = kb + FTILE_B;
#pragma unroll
        for (int i = 0; i < 8; i++) {
            int op = tid + i * 256;
            int row = op >> 4, g = op & 15;
            uint32_t off = (uint32_t)row * FROWB + (uint32_t)g * 16;
            cpa16(kb + off, Kg + ((size_t)(j * 128 + row) * DIMM) * 2 + g * 16);
            cpa16(vb + off, Vg + ((size_t)row * LL + j * 128) * 2 + g * 16);
        }
    };

    {
#pragma unroll
        for (int i = 0; i < 8; i++) {
            int op = tid + i * 256;
            int row = op >> 4, g = op & 15;
            cpa16(sb + (uint32_t)row * FROWB + (uint32_t)g * 16,
                  Qg + (size_t)row * DIMM * 2 + g * 16);
        }
        CPA_COMMIT();
        load_kv(0, 0); CPA_COMMIT();
        CPA_WAIT1();
        __syncthreads();
    }

    uint32_t aq[8][4];
    {
        uint32_t qBase = sb + (uint32_t)(warp * 16) * FROWB + aOff;
#pragma unroll
        for (int kk = 0; kk < 8; kk++)
            ldsm4(aq[kk], qBase + (uint32_t)kk * 32);
    }

    float accO[16][4];
#pragma unroll
    for (int nt = 0; nt < 16; nt++)
#pragma unroll
        for (int r = 0; r < 4; r++) accO[nt][r] = 0.f;
    float m0 = -1e30f, m1 = -1e30f, l0 = 0.f, l1 = 0.f;

    for (int j = 0; j < 8; j++) {
        const int st = j & 1;
        CPA_WAIT0();
        __syncthreads();
        if (j + 1 < 8) { load_kv((j + 1) & 1, j + 1); CPA_COMMIT(); }

        const uint32_t kBase = sb + FTILE_B + (uint32_t)st * (2 * FTILE_B) + bOff;
        const uint32_t vBase = kBase + FTILE_B;

        float sA[16][4];
#pragma unroll
        for (int nt = 0; nt < 16; nt++)
#pragma unroll
            for (int r = 0; r < 4; r++) sA[nt][r] = 0.f;
#pragma unroll
        for (int kk = 0; kk < 8; kk++) {
#pragma unroll
            for (int np = 0; np < 8; np++) {
                uint32_t bf[4];
                ldsm4(bf, kBase + (uint32_t)(np * 16) * FROWB + (uint32_t)kk * 32);
                mma16816(sA[2 * np],     aq[kk], bf[0], bf[1]);
                mma16816(sA[2 * np + 1], aq[kk], bf[2], bf[3]);
            }
        }

        float mx0 = -1e30f, mx1 = -1e30f;
#pragma unroll
        for (int nt = 0; nt < 16; nt++) {
            mx0 = fmaxf(mx0, fmaxf(sA[nt][0], sA[nt][1]));
            mx1 = fmaxf(mx1, fmaxf(sA[nt][2], sA[nt][3]));
        }
        mx0 = fmaxf(mx0, __shfl_xor_sync(0xffffffffu, mx0, 1));
        mx0 = fmaxf(mx0, __shfl_xor_sync(0xffffffffu, mx0, 2));
        mx1 = fmaxf(mx1, __shfl_xor_sync(0xffffffffu, mx1, 1));
        mx1 = fmaxf(mx1, __shfl_xor_sync(0xffffffffu, mx1, 2));
        float mn0 = fmaxf(m0, mx0), mn1 = fmaxf(m1, mx1);
        float c0 = __expf(m0 - mn0), c1 = __expf(m1 - mn1);
        l0 *= c0; l1 *= c1;
#pragma unroll
        for (int nt = 0; nt < 16; nt++) {
            accO[nt][0] *= c0; accO[nt][1] *= c0;
            accO[nt][2] *= c1; accO[nt][3] *= c1;
        }
        float s0 = 0.f, s1 = 0.f;
        uint32_t pa0[16], pa1[16];
#pragma unroll
        for (int nt = 0; nt < 16; nt++) {
            float p0 = __expf(sA[nt][0] - mn0);
            float p1 = __expf(sA[nt][1] - mn0);
            float p2 = __expf(sA[nt][2] - mn1);
            float p3 = __expf(sA[nt][3] - mn1);
            s0 += p0 + p1; s1 += p2 + p3;
            pa0[nt] = packh2(p0, p1);
            pa1[nt] = packh2(p2, p3);
        }
        s0 += __shfl_xor_sync(0xffffffffu, s0, 1);
        s0 += __shfl_xor_sync(0xffffffffu, s0, 2);
        s1 += __shfl_xor_sync(0xffffffffu, s1, 1);
        s1 += __shfl_xor_sync(0xffffffffu, s1, 2);
        l0 += s0; l1 += s1; m0 = mn0; m1 = mn1;

#pragma unroll
        for (int kk = 0; kk < 8; kk++) {
            uint32_t a[4] = { pa0[2 * kk], pa1[2 * kk], pa0[2 * kk + 1], pa1[2 * kk + 1] };
#pragma unroll
            for (int np = 0; np < 8; np++) {
                uint32_t bf[4];
                ldsm4(bf, vBase + (uint32_t)(np * 16) * FROWB + (uint32_t)kk * 32);
                mma16816(accO[2 * np],     a, bf[0], bf[1]);
                mma16816(accO[2 * np + 1], a, bf[2], bf[3]);
            }
        }
    }

    {
        float i0 = 1.f / l0, i1 = 1.f / l1;
        const int r = lane >> 2, cq = lane & 3;
        __half* Og = g_o + ((size_t)(b * LL + q0 + warp * 16)) * DIMM + h * HDIM;
#pragma unroll
        for (int nt = 0; nt < 16; nt++) {
            int col = nt * 8 + 2 * cq;
            *(__half2*)(Og + (size_t)r * DIMM + col) =
                __floats2half2_rn(accO[nt][0] * i0, accO[nt][1] * i0);
            *(__half2*)(Og + (size_t)(r + 8) * DIMM + col) =
                __floats2half2_rn(accO[nt][2] * i1, accO[nt][3] * i1);
        }
    }
}

// ============================================================
// convert helpers
// ============================================================
__global__ void cvt_h_kernel(const float* __restrict__ s, __half* __restrict__ d, size_t n4)
{
    size_t i = (size_t)blockIdx.x * blockDim.x + threadIdx.x;
    if (i < n4) {
        float4 v = ((const float4*)s)[i];
        ((__half2*)d)[2 * i]     = __floats2half2_rn(v.x, v.y);
        ((__half2*)d)[2 * i + 1] = __floats2half2_rn(v.z, v.w);
    }
}

__global__ void cvtT_kernel(const float* __restrict__ src, __half* __restrict__ dst,
                            int K, int N)
{
    __shared__ float tile[32][33];
    int k0 = blockIdx.y * 32, n0 = blockIdx.x * 32;
    int tx = threadIdx.x, ty = threadIdx.y;
#pragma unroll
    for (int i = 0; i < 32; i += 8)
        tile[ty + i][tx] = src[(size_t)(k0 + ty + i) * N + n0 + tx];
    __syncthreads();
#pragma unroll
    for (int i = 0; i < 32; i += 8)
        dst[(size_t)(n0 + ty + i) * K + k0 + tx] = __float2half_rn(tile[tx][ty + i]);
}

// V^T per head
__global__ void vtrans_kernel()
{
    __shared__ float tile[32][33];
    const int bh = blockIdx.z;
    const int b = bh / NHEADS, h = bh % NHEADS;
    const int k0 = blockIdx.x * 32, d0 = blockIdx.y * 32;
    const float* src = g_qkv + (size_t)b * LL * QKVDIM + 2 * DIMM + h * HDIM;
    __half* dst = g_vt + (size_t)bh * HDIM * LL;
    int tx = threadIdx.x, ty = threadIdx.y;
#pragma unroll
    for (int i = 0; i < 32; i += 8)
        tile[ty + i][tx] = src[(size_t)(k0 + ty + i) * QKVDIM + d0 + tx];
    __syncthreads();
#pragma unroll
    for (int i = 0; i < 32; i += 8)
        dst[(size_t)(d0 + ty + i) * LL + k0 + tx] = __float2half_rn(tile[tx][ty + i]);
}

// ============================================================
// RMSNorm + gain + RoPE -> half q (pre-scaled by SCALE), k
// ============================================================
__global__ __launch_bounds__(256) void rmsrope_kernel(
    const float* __restrict__ cosb, const float* __restrict__ sinb,
    const float* __restrict__ gq, const float* __restrict__ gk)
{
    const int t = blockIdx.x;
    const int tid = threadIdx.x;
    const float* base = g_qkv + (size_t)t * QKVDIM;

    float sq = 0.f, sk = 0.f;
    for (int i = tid; i < DIMM; i += 256) {
        float a = base[i];         sq = fmaf(a, a, sq);
        float b = base[DIMM + i];  sk = fmaf(b, b, sk);
    }
    __shared__ float r1[256], r2[256];
    r1[tid] = sq; r2[tid] = sk;
    __syncthreads();
    for (int s = 128; s > 0; s >>= 1) {
        if (tid < s) { r1[tid] += r1[tid + s]; r2[tid] += r2[tid + s]; }
        __syncthreads();
    }
    const float rq = rsqrtf(r1[0] / (float)DIMM + EPS);
    const float rk = rsqrtf(r2[0] / (float)DIMM + EPS);

    const int l = t & (LL - 1);
    const float* cl = cosb + (size_t)l * HDIM;
    const float* sl = sinb + (size_t)l * HDIM;
    __half* qo = g_q + (size_t)t * DIMM;
    __half* ko = g_k + (size_t)t * DIMM;

    for (int p = tid; p < DIMM / 2; p += 256) {
        int d = 2 * p;
        int hd = d & (HDIM - 1);
        float c = cl[hd];
        float s = sl[hd + 1];
        float x0 = base[d]     * rq * gq[d];
        float x1 = base[d + 1] * rq * gq[d + 1];
        *(__half2*)(qo + d) = __floats2half2_rn((x0 * c - x1 * s) * SCALE,
                                                (x0 * s + x1 * c) * SCALE);
        float y0 = base[DIMM + d]     * rk * gk[d];
        float y1 = base[DIMM + d + 1] * rk * gk[d + 1];
        *(__half2*)(ko + d) = __floats2half2_rn(y0 * c - y1 * s, y0 * s + y1 * c);
    }
}

// ============================================================
// launch
// ============================================================
extern "C" void kernel_launch(void* const* d_in, const int* in_sizes, int n_in,
                              void* d_out, int out_size)
{
    const float* x     = (const float*)d_in[0];
    const float* cosb  = (const float*)d_in[1];
    const float* sinb  = (const float*)d_in[2];
    const float* Wqkv  = (const float*)d_in[3];
    const float* bqkv  = (const float*)d_in[4];
    const float* gq    = (const float*)d_in[5];
    const float* gk    = (const float*)d_in[6];
    const float* Wout  = (const float*)d_in[7];
    const float* bout  = (const float*)d_in[8];
    float* out = (float*)d_out;

    void* p_qkv; cudaGetSymbolAddress(&p_qkv, g_qkv);
    void* p_o;   cudaGetSymbolAddress(&p_o,   g_o);
    void* p_wq;  cudaGetSymbolAddress(&p_wq,  g_wq);
    void* p_wo;  cudaGetSymbolAddress(&p_wo,  g_wo);
    void* p_x;   cudaGetSymbolAddress(&p_x,   g_x);

    cudaFuncSetAttribute(tc_gemm, cudaFuncAttributeMaxDynamicSharedMemorySize, GEMM_SMEM);
    cudaFuncSetAttribute(flash_kernel, cudaFuncAttributeMaxDynamicSharedMemorySize, FLASH_SMEM);

    // 0) weight transpose + fp16 rounding; activation rounding
    cvtT_kernel<<<dim3(QKVDIM / 32, DIMM / 32), dim3(32, 8)>>>(Wqkv, (__half*)p_wq, DIMM, QKVDIM);
    cvtT_kernel<<<dim3(DIMM / 32,  DIMM / 32), dim3(32, 8)>>>(Wout, (__half*)p_wo, DIMM, DIMM);
    {
        size_t n4 = (size_t)TOKENS * DIMM / 4;
        cvt_h_kernel<<<(unsigned)((n4 + 255) / 256), 256>>>(x, (__half*)p_x, n4);
    }

    // 1) QKV projection (128x128 CTAs, 128 threads)
    tc_gemm<<<dim3(TOKENS / 128, QKVDIM / 128, 1), 128, GEMM_SMEM>>>(
        (const __half*)p_x, (const __half*)p_wq, bqkv, p_qkv,
        0, 0, 0, DIMM, DIMM, QKVDIM, DIMM, 1.f, 0);

    // 2) RMSNorm + RoPE (half out, q pre-scaled), V transpose (half out)
    rmsrope_kernel<<<TOKENS, 256>>>(cosb, sinb, gq, gk);
    vtrans_kernel<<<dim3(LL / 32, HDIM / 32, BB * NHEADS), dim3(32, 8)>>>();

    // 3) fused attention
    flash_kernel<<<dim3(LL / 128, BB * NHEADS), 256, FLASH_SMEM>>>();

    // 4) out projection
    tc_gemm<<<dim3(TOKENS / 128, DIMM / 128, 1), 128, GEMM_SMEM>>>(
        (const __half*)p_o, (const __half*)p_wo, bout, out,
        0, 0, 0, DIMM, DIMM, DIMM, DIMM, 1.f, 0);
}

// round 11
// speedup vs baseline: 1.1254x; 1.0667x over previous
#include <cuda_runtime.h>
#include <cuda_fp16.h>
#include <math.h>
#include <stdint.h>

// Problem constants
#define DIMM 5120
#define NHEADS 40
#define HDIM 128
#define BB 2
#define LL 1024
#define TOKENS (BB*LL)          // 2048
#define QKVDIM (3*DIMM)         // 15360
#define SCALE 0.08838834764831845f
#define EPS 1e-6f

// -------- scratch (static device globals; no runtime allocation) --------
__device__ float  g_qkv[(size_t)TOKENS * QKVDIM];           // 125.8 MB f32
__device__ __half g_q[(size_t)TOKENS * DIMM];               // scaled by SCALE
__device__ __half g_k[(size_t)TOKENS * DIMM];
__device__ __half g_o[(size_t)TOKENS * DIMM];
__device__ __half g_vt[(size_t)BB * NHEADS * HDIM * LL];    // V^T per head
__device__ __half g_wq[(size_t)QKVDIM * DIMM];              // W_qkv^T [N,K]
__device__ __half g_wo[(size_t)DIMM * DIMM];                // W_out^T [N,K]
__device__ __half g_x[(size_t)TOKENS * DIMM];               // x, half

// ============================================================
// helpers
// ============================================================
__device__ __forceinline__ uint32_t smem_u32(const void* p) {
    uint32_t a;
    asm("{ .reg .u64 t; cvta.to.shared.u64 t, %1; cvt.u32.u64 %0, t; }" : "=r"(a) : "l"(p));
    return a;
}
__device__ __forceinline__ void cpa16(uint32_t dst, const void* src) {
    asm volatile("cp.async.cg.shared.global [%0], [%1], 16;" :: "r"(dst), "l"(src));
}
#define CPA_COMMIT() asm volatile("cp.async.commit_group;" ::: "memory")
#define CPA_WAIT1()  asm volatile("cp.async.wait_group 1;" ::: "memory")
#define CPA_WAIT0()  asm volatile("cp.async.wait_group 0;" ::: "memory")

// fp16 m16n8k16, f32 accum
__device__ __forceinline__ void mma16816(float* d, const uint32_t* a, uint32_t b0, uint32_t b1) {
    asm volatile(
        "mma.sync.aligned.m16n8k16.row.col.f32.f16.f16.f32 "
        "{%0,%1,%2,%3}, {%4,%5,%6,%7}, {%8,%9}, {%0,%1,%2,%3};"
        : "+f"(d[0]), "+f"(d[1]), "+f"(d[2]), "+f"(d[3])
        : "r"(a[0]), "r"(a[1]), "r"(a[2]), "r"(a[3]), "r"(b0), "r"(b1));
}
__device__ __forceinline__ void ldsm4(uint32_t* r, uint32_t addr) {
    asm volatile("ldmatrix.sync.aligned.m8n8.x4.shared.b16 {%0,%1,%2,%3}, [%4];"
        : "=r"(r[0]), "=r"(r[1]), "=r"(r[2]), "=r"(r[3]) : "r"(addr));
}
__device__ __forceinline__ uint32_t packh2(float x, float y) {
    __half2 h = __floats2half2_rn(x, y);
    return *(uint32_t*)&h;
}

// ============================================================
// Persistent fp16 mma.sync GEMM (R8 tile shape):
//   C[m,n] = alpha * A[m,:K] * Bt[n,:K]^T (+ bias[n])
// CTA tile 128x128, 256 threads, 8 warps 2(M)x4(N), warp tile 64x32.
// K-chunk 64, 3-stage cp.async, 2 CTAs/SM. Grid = 296 persistent CTAs;
// each loops over tiles (M-fastest order) -> no wave quantization.
// ============================================================
#define KC 64
#define ROWB 144
#define TILE_B (128 * ROWB)
#define STAGE_B (2 * TILE_B)
#define NSTG 3
#define GEMM_SMEM (NSTG * STAGE_B)          // 110592 B
#define GEMM_GRID 296

__global__ __launch_bounds__(256, 2) void tc_gemm(
    const __half* __restrict__ A, const __half* __restrict__ Bt,
    const float* __restrict__ bias, void* __restrict__ Cv,
    int lda, int ldb, int ldc, int K, float alpha, int store_half,
    int mtiles, int ntot)
{
    extern __shared__ char sm[];
    const uint32_t sb = smem_u32(sm);

    const int tid  = threadIdx.x;
    const int warp = tid >> 5;
    const int lane = tid & 31;
    const int wm = warp >> 2;          // 0..1
    const int wn = warp & 3;           // 0..3

    const uint32_t aOff = (uint32_t)(lane & 15) * ROWB + (uint32_t)(lane >> 4) * 16;
    const uint32_t bOff = (uint32_t)((lane & 7) + ((lane >> 4) & 1) * 8) * ROWB
                        + (uint32_t)((lane >> 3) & 1) * 16;

    const int nch = K / KC;

    for (int t = blockIdx.x; t < ntot; t += gridDim.x) {
        const int m0 = (t % mtiles) * 128;
        const int n0 = (t / mtiles) * 128;

        float acc[4][4][4];
#pragma unroll
        for (int mt = 0; mt < 4; mt++)
#pragma unroll
            for (int nt = 0; nt < 4; nt++)
#pragma unroll
                for (int r = 0; r < 4; r++) acc[mt][nt][r] = 0.f;

        auto load_chunk = [&](int st, int kc) {
            uint32_t base = sb + (uint32_t)st * STAGE_B;
#pragma unroll
            for (int i = 0; i < 4; i++) {
                int op = tid + i * 256;
                int row = op >> 3, g = op & 7;
                uint32_t off = (uint32_t)row * ROWB + (uint32_t)g * 16;
                cpa16(base + off,
                      (const char*)A + ((size_t)(m0 + row) * lda + kc + g * 8) * 2);
                cpa16(base + TILE_B + off,
                      (const char*)Bt + ((size_t)(n0 + row) * ldb + kc + g * 8) * 2);
            }
        };

        load_chunk(0, 0);       CPA_COMMIT();
        if (nch > 1) { load_chunk(1, KC); CPA_COMMIT(); }

        for (int c = 0; c < nch; c++) {
            const int st = c % NSTG;
            if (c + 1 < nch) { CPA_WAIT1(); } else { CPA_WAIT0(); }
            __syncthreads();
            if (c + 2 < nch) { load_chunk((c + 2) % NSTG, (c + 2) * KC); CPA_COMMIT(); }

            const uint32_t aBase = sb + (uint32_t)st * STAGE_B
                                 + (uint32_t)(wm * 64) * ROWB + aOff;
            const uint32_t bBase = sb + (uint32_t)st * STAGE_B + TILE_B
                                 + (uint32_t)(wn * 32) * ROWB + bOff;

#pragma unroll
            for (int s = 0; s < 4; s++) {
                const uint32_t kb = (uint32_t)s * 32;
                uint32_t af[4][4];
#pragma unroll
                for (int mt = 0; mt < 4; mt++)
                    ldsm4(af[mt], aBase + (uint32_t)(mt * 16) * ROWB + kb);
                uint32_t bf[2][4];
#pragma unroll
                for (int np = 0; np < 2; np++)
                    ldsm4(bf[np], bBase + (uint32_t)(np * 16) * ROWB + kb);
#pragma unroll
                for (int mt = 0; mt < 4; mt++)
#pragma unroll
                    for (int nt = 0; nt < 4; nt++)
                        mma16816(acc[mt][nt], af[mt],
                                 bf[nt >> 1][(nt & 1) * 2], bf[nt >> 1][(nt & 1) * 2 + 1]);
            }
        }

        // epilogue
        {
            const int r = lane >> 2, cq = lane & 3;
#pragma unroll
            for (int mt = 0; mt < 4; mt++) {
                int row = m0 + wm * 64 + mt * 16 + r;
#pragma unroll
                for (int nt = 0; nt < 4; nt++) {
                    int col = n0 + wn * 32 + nt * 8 + 2 * cq;
                    float bvx = 0.f, bvy = 0.f;
                    if (bias) { float2 bv = *(const float2*)(bias + col); bvx = bv.x; bvy = bv.y; }
                    float o0x = fmaf(acc[mt][nt][0], alpha, bvx);
                    float o0y = fmaf(acc[mt][nt][1], alpha, bvy);
                    float o1x = fmaf(acc[mt][nt][2], alpha, bvx);
                    float o1y = fmaf(acc[mt][nt][3], alpha, bvy);
                    if (store_half) {
                        __half* C = (__half*)Cv;
                        *(__half2*)(C + (size_t)row * ldc + col) = __floats2half2_rn(o0x, o0y);
                        *(__half2*)(C + (size_t)(row + 8) * ldc + col) = __floats2half2_rn(o1x, o1y);
                    } else {
                        float* C = (float*)Cv;
                        *(float2*)(C + (size_t)row * ldc + col) = make_float2(o0x, o0y);
                        *(float2*)(C + (size_t)(row + 8) * ldc + col) = make_float2(o1x, o1y);
                    }
                }
            }
        }
        __syncthreads();   // protect smem stages before next tile's prologue
    }
}

// ============================================================
// Persistent flash attention: work item = (q-tile, bh).
// CTA = 128 q rows x one (b,h); 8 warps x 16 rows; online softmax.
// Grid = 148 persistent CTAs over 640 items.
// ============================================================
#define FROWB 272
#define FTILE_B (128 * FROWB)               // 34816
#define FLASH_SMEM (5 * FTILE_B)            // 174080: Q + 2x(K+V)
#define FLASH_GRID 148
#define FLASH_ITEMS (BB * NHEADS * (LL / 128))   // 640

__global__ __launch_bounds__(256, 1) void flash_kernel()
{
    extern __shared__ char sm[];
    const uint32_t sb = smem_u32(sm);
    const int tid = threadIdx.x, warp = tid >> 5, lane = tid & 31;

    const uint32_t aOff = (uint32_t)(lane & 15) * FROWB + (uint32_t)(lane >> 4) * 16;
    const uint32_t bOff = (uint32_t)((lane & 7) + ((lane >> 4) & 1) * 8) * FROWB
                        + (uint32_t)((lane >> 3) & 1) * 16;

    for (int it = blockIdx.x; it < FLASH_ITEMS; it += gridDim.x) {
        const int q0 = (it & 7) * 128;          // LL/128 = 8 q-tiles, fastest
        const int bh = it >> 3;
        const int b = bh / NHEADS, h = bh % NHEADS;

        const char* Qg = (const char*)(g_q + ((size_t)(b * LL + q0)) * DIMM + h * HDIM);
        const char* Kg = (const char*)(g_k + ((size_t)(b * LL)) * DIMM + h * HDIM);
        const char* Vg = (const char*)(g_vt + (size_t)bh * HDIM * LL);

        auto load_kv = [&](int st, int j) {
            uint32_t kb = sb + FTILE_B + (uint32_t)st * (2 * FTILE_B);
            uint32_t vb = kb + FTILE_B;
#pragma unroll
            for (int i = 0; i < 8; i++) {
                int op = tid + i * 256;
                int row = op >> 4, g = op & 15;
                uint32_t off = (uint32_t)row * FROWB + (uint32_t)g * 16;
                cpa16(kb + off, Kg + ((size_t)(j * 128 + row) * DIMM) * 2 + g * 16);
                cpa16(vb + off, Vg + ((size_t)row * LL + j * 128) * 2 + g * 16);
            }
        };

        // prologue: Q tile + KV block 0
        {
#pragma unroll
            for (int i = 0; i < 8; i++) {
                int op = tid + i * 256;
                int row = op >> 4, g = op & 15;
                cpa16(sb + (uint32_t)row * FROWB + (uint32_t)g * 16,
                      Qg + (size_t)row * DIMM * 2 + g * 16);
            }
            CPA_COMMIT();
            load_kv(0, 0); CPA_COMMIT();
            CPA_WAIT1();            // Q resident
            __syncthreads();
        }

        uint32_t aq[8][4];
        {
            uint32_t qBase = sb + (uint32_t)(warp * 16) * FROWB + aOff;
#pragma unroll
            for (int kk = 0; kk < 8; kk++)
                ldsm4(aq[kk], qBase + (uint32_t)kk * 32);
        }

        float accO[16][4];
#pragma unroll
        for (int nt = 0; nt < 16; nt++)
#pragma unroll
            for (int r = 0; r < 4; r++) accO[nt][r] = 0.f;
        float m0 = -1e30f, m1 = -1e30f, l0 = 0.f, l1 = 0.f;

        for (int j = 0; j < 8; j++) {
            const int st = j & 1;
            CPA_WAIT0();
            __syncthreads();
            if (j + 1 < 8) { load_kv((j + 1) & 1, j + 1); CPA_COMMIT(); }

            const uint32_t kBase = sb + FTILE_B + (uint32_t)st * (2 * FTILE_B) + bOff;
            const uint32_t vBase = kBase + FTILE_B;

            float sA[16][4];
#pragma unroll
            for (int nt = 0; nt < 16; nt++)
#pragma unroll
                for (int r = 0; r < 4; r++) sA[nt][r] = 0.f;
#pragma unroll
            for (int kk = 0; kk < 8; kk++) {
#pragma unroll
                for (int np = 0; np < 8; np++) {
                    uint32_t bf[4];
                    ldsm4(bf, kBase + (uint32_t)(np * 16) * FROWB + (uint32_t)kk * 32);
                    mma16816(sA[2 * np],     aq[kk], bf[0], bf[1]);
                    mma16816(sA[2 * np + 1], aq[kk], bf[2], bf[3]);
                }
            }

            float mx0 = -1e30f, mx1 = -1e30f;
#pragma unroll
            for (int nt = 0; nt < 16; nt++) {
                mx0 = fmaxf(mx0, fmaxf(sA[nt][0], sA[nt][1]));
                mx1 = fmaxf(mx1, fmaxf(sA[nt][2], sA[nt][3]));
            }
            mx0 = fmaxf(mx0, __shfl_xor_sync(0xffffffffu, mx0, 1));
            mx0 = fmaxf(mx0, __shfl_xor_sync(0xffffffffu, mx0, 2));
            mx1 = fmaxf(mx1, __shfl_xor_sync(0xffffffffu, mx1, 1));
            mx1 = fmaxf(mx1, __shfl_xor_sync(0xffffffffu, mx1, 2));
            float mn0 = fmaxf(m0, mx0), mn1 = fmaxf(m1, mx1);
            float c0 = __expf(m0 - mn0), c1 = __expf(m1 - mn1);
            l0 *= c0; l1 *= c1;
#pragma unroll
            for (int nt = 0; nt < 16; nt++) {
                accO[nt][0] *= c0; accO[nt][1] *= c0;
                accO[nt][2] *= c1; accO[nt][3] *= c1;
            }
            float s0 = 0.f, s1 = 0.f;
            uint32_t pa0[16], pa1[16];
#pragma unroll
            for (int nt = 0; nt < 16; nt++) {
                float p0 = __expf(sA[nt][0] - mn0);
                float p1 = __expf(sA[nt][1] - mn0);
                float p2 = __expf(sA[nt][2] - mn1);
                float p3 = __expf(sA[nt][3] - mn1);
                s0 += p0 + p1; s1 += p2 + p3;
                pa0[nt] = packh2(p0, p1);
                pa1[nt] = packh2(p2, p3);
            }
            s0 += __shfl_xor_sync(0xffffffffu, s0, 1);
            s0 += __shfl_xor_sync(0xffffffffu, s0, 2);
            s1 += __shfl_xor_sync(0xffffffffu, s1, 1);
            s1 += __shfl_xor_sync(0xffffffffu, s1, 2);
            l0 += s0; l1 += s1; m0 = mn0; m1 = mn1;

#pragma unroll
            for (int kk = 0; kk < 8; kk++) {
                uint32_t a[4] = { pa0[2 * kk], pa1[2 * kk], pa0[2 * kk + 1], pa1[2 * kk + 1] };
#pragma unroll
                for (int np = 0; np < 8; np++) {
                    uint32_t bf[4];
                    ldsm4(bf, vBase + (uint32_t)(np * 16) * FROWB + (uint32_t)kk * 32);
                    mma16816(accO[2 * np],     a, bf[0], bf[1]);
                    mma16816(accO[2 * np + 1], a, bf[2], bf[3]);
                }
            }
        }

        // epilogue: O /= l, write half
        {
            float i0 = 1.f / l0, i1 = 1.f / l1;
            const int r = lane >> 2, cq = lane & 3;
            __half* Og = g_o + ((size_t)(b * LL + q0 + warp * 16)) * DIMM + h * HDIM;
#pragma unroll
            for (int nt = 0; nt < 16; nt++) {
                int col = nt * 8 + 2 * cq;
                *(__half2*)(Og + (size_t)r * DIMM + col) =
                    __floats2half2_rn(accO[nt][0] * i0, accO[nt][1] * i0);
                *(__half2*)(Og + (size_t)(r + 8) * DIMM + col) =
                    __floats2half2_rn(accO[nt][2] * i1, accO[nt][3] * i1);
            }
        }
        // no extra sync needed: next item's prologue sync orders smem reuse
    }
}

// ============================================================
// convert helpers
// ============================================================
__global__ void cvt_h_kernel(const float* __restrict__ s, __half* __restrict__ d, size_t n4)
{
    size_t i = (size_t)blockIdx.x * blockDim.x + threadIdx.x;
    if (i < n4) {
        float4 v = ((const float4*)s)[i];
        ((__half2*)d)[2 * i]     = __floats2half2_rn(v.x, v.y);
        ((__half2*)d)[2 * i + 1] = __floats2half2_rn(v.z, v.w);
    }
}

__global__ void cvtT_kernel(const float* __restrict__ src, __half* __restrict__ dst,
                            int K, int N)
{
    __shared__ float tile[32][33];
    int k0 = blockIdx.y * 32, n0 = blockIdx.x * 32;
    int tx = threadIdx.x, ty = threadIdx.y;
#pragma unroll
    for (int i = 0; i < 32; i += 8)
        tile[ty + i][tx] = src[(size_t)(k0 + ty + i) * N + n0 + tx];
    __syncthreads();
#pragma unroll
    for (int i = 0; i < 32; i += 8)
        dst[(size_t)(n0 + ty + i) * K + k0 + tx] = __float2half_rn(tile[tx][ty + i]);
}

// V^T per head
__global__ void vtrans_kernel()
{
    __shared__ float tile[32][33];
    const int bh = blockIdx.z;
    const int b = bh / NHEADS, h = bh % NHEADS;
    const int k0 = blockIdx.x * 32, d0 = blockIdx.y * 32;
    const float* src = g_qkv + (size_t)b * LL * QKVDIM + 2 * DIMM + h * HDIM;
    __half* dst = g_vt + (size_t)bh * HDIM * LL;
    int tx = threadIdx.x, ty = threadIdx.y;
#pragma unroll
    for (int i = 0; i < 32; i += 8)
        tile[ty + i][tx] = src[(size_t)(k0 + ty + i) * QKVDIM + d0 + tx];
    __syncthreads();
#pragma unroll
    for (int i = 0; i < 32; i += 8)
        dst[(size_t)(d0 + ty + i) * LL + k0 + tx] = __float2half_rn(tile[tx][ty + i]);
}

// ============================================================
// RMSNorm + gain + RoPE -> half q (pre-scaled by SCALE), k
// ============================================================
__global__ __launch_bounds__(256) void rmsrope_kernel(
    const float* __restrict__ cosb, const float* __restrict__ sinb,
    const float* __restrict__ gq, const float* __restrict__ gk)
{
    const int t = blockIdx.x;
    const int tid = threadIdx.x;
    const float* base = g_qkv + (size_t)t * QKVDIM;

    float sq = 0.f, sk = 0.f;
    for (int i = tid; i < DIMM; i += 256) {
        float a = base[i];         sq = fmaf(a, a, sq);
        float b = base[DIMM + i];  sk = fmaf(b, b, sk);
    }
    __shared__ float r1[256], r2[256];
    r1[tid] = sq; r2[tid] = sk;
    __syncthreads();
    for (int s = 128; s > 0; s >>= 1) {
        if (tid < s) { r1[tid] += r1[tid + s]; r2[tid] += r2[tid + s]; }
        __syncthreads();
    }
    const float rq = rsqrtf(r1[0] / (float)DIMM + EPS);
    const float rk = rsqrtf(r2[0] / (float)DIMM + EPS);

    const int l = t & (LL - 1);
    const float* cl = cosb + (size_t)l * HDIM;
    const float* sl = sinb + (size_t)l * HDIM;
    __half* qo = g_q + (size_t)t * DIMM;
    __half* ko = g_k + (size_t)t * DIMM;

    for (int p = tid; p < DIMM / 2; p += 256) {
        int d = 2 * p;
        int hd = d & (HDIM - 1);
        float c = cl[hd];
        float s = sl[hd + 1];
        float x0 = base[d]     * rq * gq[d];
        float x1 = base[d + 1] * rq * gq[d + 1];
        *(__half2*)(qo + d) = __floats2half2_rn((x0 * c - x1 * s) * SCALE,
                                                (x0 * s + x1 * c) * SCALE);
        float y0 = base[DIMM + d]     * rk * gk[d];
        float y1 = base[DIMM + d + 1] * rk * gk[d + 1];
        *(__half2*)(ko + d) = __floats2half2_rn(y0 * c - y1 * s, y0 * s + y1 * c);
    }
}

// ============================================================
// launch
// ============================================================
extern "C" void kernel_launch(void* const* d_in, const int* in_sizes, int n_in,
                              void* d_out, int out_size)
{
    const float* x     = (const float*)d_in[0];
    const float* cosb  = (const float*)d_in[1];
    const float* sinb  = (const float*)d_in[2];
    const float* Wqkv  = (const float*)d_in[3];
    const float* bqkv  = (const float*)d_in[4];
    const float* gq    = (const float*)d_in[5];
    const float* gk    = (const float*)d_in[6];
    const float* Wout  = (const float*)d_in[7];
    const float* bout  = (const float*)d_in[8];
    float* out = (float*)d_out;

    void* p_qkv; cudaGetSymbolAddress(&p_qkv, g_qkv);
    void* p_o;   cudaGetSymbolAddress(&p_o,   g_o);
    void* p_wq;  cudaGetSymbolAddress(&p_wq,  g_wq);
    void* p_wo;  cudaGetSymbolAddress(&p_wo,  g_wo);
    void* p_x;   cudaGetSymbolAddress(&p_x,   g_x);

    cudaFuncSetAttribute(tc_gemm, cudaFuncAttributeMaxDynamicSharedMemorySize, GEMM_SMEM);
    cudaFuncSetAttribute(flash_kernel, cudaFuncAttributeMaxDynamicSharedMemorySize, FLASH_SMEM);

    // 0) weight transpose + fp16 rounding; activation rounding
    cvtT_kernel<<<dim3(QKVDIM / 32, DIMM / 32), dim3(32, 8)>>>(Wqkv, (__half*)p_wq, DIMM, QKVDIM);
    cvtT_kernel<<<dim3(DIMM / 32,  DIMM / 32), dim3(32, 8)>>>(Wout, (__half*)p_wo, DIMM, DIMM);
    {
        size_t n4 = (size_t)TOKENS * DIMM / 4;
        cvt_h_kernel<<<(unsigned)((n4 + 255) / 256), 256>>>(x, (__half*)p_x, n4);
    }

    // 1) QKV projection: persistent, 16 M-tiles x 120 N-tiles = 1920
    tc_gemm<<<GEMM_GRID, 256, GEMM_SMEM>>>(
        (const __half*)p_x, (const __half*)p_wq, bqkv, p_qkv,
        DIMM, DIMM, QKVDIM, DIMM, 1.f, 0,
        TOKENS / 128, (TOKENS / 128) * (QKVDIM / 128));

    // 2) RMSNorm + RoPE (half out, q pre-scaled), V transpose (half out)
    rmsrope_kernel<<<TOKENS, 256>>>(cosb, sinb, gq, gk);
    vtrans_kernel<<<dim3(LL / 32, HDIM / 32, BB * NHEADS), dim3(32, 8)>>>();

    // 3) fused attention: persistent over 640 items
    flash_kernel<<<FLASH_GRID, 256, FLASH_SMEM>>>();

    // 4) out projection: persistent, 16 x 40 = 640 tiles
    tc_gemm<<<GEMM_GRID, 256, GEMM_SMEM>>>(
        (const __half*)p_o, (const __half*)p_wo, bout, out,
        DIMM, DIMM, DIMM, DIMM, 1.f, 0,
        TOKENS / 128, (TOKENS / 128) * (DIMM / 128));
}

// round 12
// speedup vs baseline: 1.1495x; 1.0214x over previous
#include <cuda_runtime.h>
#include <cuda_fp16.h>
#include <math.h>
#include <stdint.h>

// Problem constants
#define DIMM 5120
#define NHEADS 40
#define HDIM 128
#define BB 2
#define LL 1024
#define TOKENS (BB*LL)          // 2048
#define QKVDIM (3*DIMM)         // 15360
#define SCALE 0.08838834764831845f
#define EPS 1e-6f

// -------- scratch (static device globals; no runtime allocation) --------
__device__ float  g_qkv[(size_t)TOKENS * QKVDIM];           // 125.8 MB f32
__device__ __half g_q[(size_t)TOKENS * DIMM];               // scaled by SCALE
__device__ __half g_k[(size_t)TOKENS * DIMM];
__device__ __half g_o[(size_t)TOKENS * DIMM];
__device__ __half g_vt[(size_t)BB * NHEADS * HDIM * LL];    // V^T per head
__device__ __half g_wq[(size_t)QKVDIM * DIMM];              // W_qkv^T [N,K]
__device__ __half g_wo[(size_t)DIMM * DIMM];                // W_out^T [N,K]
__device__ __half g_x[(size_t)TOKENS * DIMM];               // x, half

// ============================================================
// helpers
// ============================================================
__device__ __forceinline__ uint32_t smem_u32(const void* p) {
    uint32_t a;
    asm("{ .reg .u64 t; cvta.to.shared.u64 t, %1; cvt.u32.u64 %0, t; }" : "=r"(a) : "l"(p));
    return a;
}
__device__ __forceinline__ void cpa16(uint32_t dst, const void* src) {
    asm volatile("cp.async.cg.shared.global [%0], [%1], 16;" :: "r"(dst), "l"(src));
}
#define CPA_COMMIT() asm volatile("cp.async.commit_group;" ::: "memory")
#define CPA_WAIT1()  asm volatile("cp.async.wait_group 1;" ::: "memory")
#define CPA_WAIT0()  asm volatile("cp.async.wait_group 0;" ::: "memory")

// fp16 m16n8k16, f32 accum
__device__ __forceinline__ void mma16816(float* d, const uint32_t* a, uint32_t b0, uint32_t b1) {
    asm volatile(
        "mma.sync.aligned.m16n8k16.row.col.f32.f16.f16.f32 "
        "{%0,%1,%2,%3}, {%4,%5,%6,%7}, {%8,%9}, {%0,%1,%2,%3};"
        : "+f"(d[0]), "+f"(d[1]), "+f"(d[2]), "+f"(d[3])
        : "r"(a[0]), "r"(a[1]), "r"(a[2]), "r"(a[3]), "r"(b0), "r"(b1));
}
__device__ __forceinline__ void ldsm4(uint32_t* r, uint32_t addr) {
    asm volatile("ldmatrix.sync.aligned.m8n8.x4.shared.b16 {%0,%1,%2,%3}, [%4];"
        : "=r"(r[0]), "=r"(r[1]), "=r"(r[2]), "=r"(r[3]) : "r"(addr));
}
__device__ __forceinline__ uint32_t packh2(float x, float y) {
    __half2 h = __floats2half2_rn(x, y);
    return *(uint32_t*)&h;
}

// ============================================================
// fp16 mma.sync GEMM (R8-exact, non-persistent):
//   C[z][m,n] = alpha * A[z][m,:K] * Bt[z][n,:K]^T (+ bias[n])
// CTA tile 128x128, 256 threads, 8 warps 2(M)x4(N), warp tile 64x32.
// K-chunk 64, 3-stage cp.async, 2 CTAs/SM.
// Grid: blockIdx.x = M tile, blockIdx.y = N tile.
// ============================================================
#define KC 64
#define ROWB 144
#define TILE_B (128 * ROWB)
#define STAGE_B (2 * TILE_B)
#define NSTG 3
#define GEMM_SMEM (NSTG * STAGE_B)          // 110592 B

__global__ __launch_bounds__(256) void tc_gemm(
    const __half* __restrict__ A, const __half* __restrict__ Bt,
    const float* __restrict__ bias, void* __restrict__ Cv,
    long sAz, long sBz, long sCz,
    int lda, int ldb, int ldc, int K, float alpha, int store_half)
{
    extern __shared__ char sm[];
    const uint32_t sb = smem_u32(sm);

    A  += (size_t)blockIdx.z * sAz;
    Bt += (size_t)blockIdx.z * sBz;

    const int tid  = threadIdx.x;
    const int warp = tid >> 5;
    const int lane = tid & 31;
    const int wm = warp >> 2;
    const int wn = warp & 3;
    const int m0 = blockIdx.x * 128;
    const int n0 = blockIdx.y * 128;

    const uint32_t aOff = (uint32_t)(lane & 15) * ROWB + (uint32_t)(lane >> 4) * 16;
    const uint32_t bOff = (uint32_t)((lane & 7) + ((lane >> 4) & 1) * 8) * ROWB
                        + (uint32_t)((lane >> 3) & 1) * 16;

    float acc[4][4][4];
#pragma unroll
    for (int mt = 0; mt < 4; mt++)
#pragma unroll
        for (int nt = 0; nt < 4; nt++)
#pragma unroll
            for (int r = 0; r < 4; r++) acc[mt][nt][r] = 0.f;

    const int nch = K / KC;

    auto load_chunk = [&](int st, int kc) {
        uint32_t base = sb + (uint32_t)st * STAGE_B;
#pragma unroll
        for (int i = 0; i < 4; i++) {
            int op = tid + i * 256;
            int row = op >> 3, g = op & 7;
            uint32_t off = (uint32_t)row * ROWB + (uint32_t)g * 16;
            cpa16(base + off,
                  (const char*)A + ((size_t)(m0 + row) * lda + kc + g * 8) * 2);
            cpa16(base + TILE_B + off,
                  (const char*)Bt + ((size_t)(n0 + row) * ldb + kc + g * 8) * 2);
        }
    };

    load_chunk(0, 0);       CPA_COMMIT();
    if (nch > 1) { load_chunk(1, KC); CPA_COMMIT(); }

    for (int c = 0; c < nch; c++) {
        const int st = c % NSTG;
        if (c + 1 < nch) { CPA_WAIT1(); } else { CPA_WAIT0(); }
        __syncthreads();
        if (c + 2 < nch) { load_chunk((c + 2) % NSTG, (c + 2) * KC); CPA_COMMIT(); }

        const uint32_t aBase = sb + (uint32_t)st * STAGE_B
                             + (uint32_t)(wm * 64) * ROWB + aOff;
        const uint32_t bBase = sb + (uint32_t)st * STAGE_B + TILE_B
                             + (uint32_t)(wn * 32) * ROWB + bOff;

#pragma unroll
        for (int s = 0; s < 4; s++) {
            const uint32_t kb = (uint32_t)s * 32;
            uint32_t af[4][4];
#pragma unroll
            for (int mt = 0; mt < 4; mt++)
                ldsm4(af[mt], aBase + (uint32_t)(mt * 16) * ROWB + kb);
            uint32_t bf[2][4];
#pragma unroll
            for (int np = 0; np < 2; np++)
                ldsm4(bf[np], bBase + (uint32_t)(np * 16) * ROWB + kb);
#pragma unroll
            for (int mt = 0; mt < 4; mt++)
#pragma unroll
                for (int nt = 0; nt < 4; nt++)
                    mma16816(acc[mt][nt], af[mt],
                             bf[nt >> 1][(nt & 1) * 2], bf[nt >> 1][(nt & 1) * 2 + 1]);
        }
    }

    {
        const int r = lane >> 2, cq = lane & 3;
#pragma unroll
        for (int mt = 0; mt < 4; mt++) {
            int row = m0 + wm * 64 + mt * 16 + r;
#pragma unroll
            for (int nt = 0; nt < 4; nt++) {
                int col = n0 + wn * 32 + nt * 8 + 2 * cq;
                float bvx = 0.f, bvy = 0.f;
                if (bias) { float2 bv = *(const float2*)(bias + col); bvx = bv.x; bvy = bv.y; }
                float o0x = fmaf(acc[mt][nt][0], alpha, bvx);
                float o0y = fmaf(acc[mt][nt][1], alpha, bvy);
                float o1x = fmaf(acc[mt][nt][2], alpha, bvx);
                float o1y = fmaf(acc[mt][nt][3], alpha, bvy);
                if (store_half) {
                    __half* C = (__half*)Cv + (size_t)blockIdx.z * sCz;
                    *(__half2*)(C + (size_t)row * ldc + col) = __floats2half2_rn(o0x, o0y);
                    *(__half2*)(C + (size_t)(row + 8) * ldc + col) = __floats2half2_rn(o1x, o1y);
                } else {
                    float* C = (float*)Cv + (size_t)blockIdx.z * sCz;
                    *(float2*)(C + (size_t)row * ldc + col) = make_float2(o0x, o0y);
                    *(float2*)(C + (size_t)(row + 8) * ldc + col) = make_float2(o1x, o1y);
                }
            }
        }
    }
}

// ============================================================
// Persistent flash attention (R11 version): work item = (q-tile, bh).
// CTA = 128 q rows x one (b,h); 8 warps x 16 rows; online softmax.
// Grid = 148 persistent CTAs over 640 items.
// ============================================================
#define FROWB 272
#define FTILE_B (128 * FROWB)               // 34816
#define FLASH_SMEM (5 * FTILE_B)            // 174080: Q + 2x(K+V)
#define FLASH_GRID 148
#define FLASH_ITEMS (BB * NHEADS * (LL / 128))   // 640

__global__ __launch_bounds__(256, 1) void flash_kernel()
{
    extern __shared__ char sm[];
    const uint32_t sb = smem_u32(sm);
    const int tid = threadIdx.x, warp = tid >> 5, lane = tid & 31;

    const uint32_t aOff = (uint32_t)(lane & 15) * FROWB + (uint32_t)(lane >> 4) * 16;
    const uint32_t bOff = (uint32_t)((lane & 7) + ((lane >> 4) & 1) * 8) * FROWB
                        + (uint32_t)((lane >> 3) & 1) * 16;

    for (int it = blockIdx.x; it < FLASH_ITEMS; it += gridDim.x) {
        const int q0 = (it & 7) * 128;          // 8 q-tiles fastest -> K/V L2 reuse
        const int bh = it >> 3;
        const int b = bh / NHEADS, h = bh % NHEADS;

        const char* Qg = (const char*)(g_q + ((size_t)(b * LL + q0)) * DIMM + h * HDIM);
        const char* Kg = (const char*)(g_k + ((size_t)(b * LL)) * DIMM + h * HDIM);
        const char* Vg = (const char*)(g_vt + (size_t)bh * HDIM * LL);

        auto load_kv = [&](int st, int j) {
            uint32_t kb = sb + FTILE_B + (uint32_t)st * (2 * FTILE_B);
            uint32_t vb = kb + FTILE_B;
#pragma unroll
            for (int i = 0; i < 8; i++) {
                int op = tid + i * 256;
                int row = op >> 4, g = op & 15;
                uint32_t off = (uint32_t)row * FROWB + (uint32_t)g * 16;
                cpa16(kb + off, Kg + ((size_t)(j * 128 + row) * DIMM) * 2 + g * 16);
                cpa16(vb + off, Vg + ((size_t)row * LL + j * 128) * 2 + g * 16);
            }
        };

        // prologue: Q tile + KV block 0
        {
#pragma unroll
            for (int i = 0; i < 8; i++) {
                int op = tid + i * 256;
                int row = op >> 4, g = op & 15;
                cpa16(sb + (uint32_t)row * FROWB + (uint32_t)g * 16,
                      Qg + (size_t)row * DIMM * 2 + g * 16);
            }
            CPA_COMMIT();
            load_kv(0, 0); CPA_COMMIT();
            CPA_WAIT1();            // Q resident
            __syncthreads();
        }

        uint32_t aq[8][4];
        {
            uint32_t qBase = sb + (uint32_t)(warp * 16) * FROWB + aOff;
#pragma unroll
            for (int kk = 0; kk < 8; kk++)
                ldsm4(aq[kk], qBase + (uint32_t)kk * 32);
        }

        float accO[16][4];
#pragma unroll
        for (int nt = 0; nt < 16; nt++)
#pragma unroll
            for (int r = 0; r < 4; r++) accO[nt][r] = 0.f;
        float m0 = -1e30f, m1 = -1e30f, l0 = 0.f, l1 = 0.f;

        for (int j = 0; j < 8; j++) {
            const int st = j & 1;
            CPA_WAIT0();
            __syncthreads();
            if (j + 1 < 8) { load_kv((j + 1) & 1, j + 1); CPA_COMMIT(); }

            const uint32_t kBase = sb + FTILE_B + (uint32_t)st * (2 * FTILE_B) + bOff;
            const uint32_t vBase = kBase + FTILE_B;

            float sA[16][4];
#pragma unroll
            for (int nt = 0; nt < 16; nt++)
#pragma unroll
                for (int r = 0; r < 4; r++) sA[nt][r] = 0.f;
#pragma unroll
            for (int kk = 0; kk < 8; kk++) {
#pragma unroll
                for (int np = 0; np < 8; np++) {
                    uint32_t bf[4];
                    ldsm4(bf, kBase + (uint32_t)(np * 16) * FROWB + (uint32_t)kk * 32);
                    mma16816(sA[2 * np],     aq[kk], bf[0], bf[1]);
                    mma16816(sA[2 * np + 1], aq[kk], bf[2], bf[3]);
                }
            }

            float mx0 = -1e30f, mx1 = -1e30f;
#pragma unroll
            for (int nt = 0; nt < 16; nt++) {
                mx0 = fmaxf(mx0, fmaxf(sA[nt][0], sA[nt][1]));
                mx1 = fmaxf(mx1, fmaxf(sA[nt][2], sA[nt][3]));
            }
            mx0 = fmaxf(mx0, __shfl_xor_sync(0xffffffffu, mx0, 1));
            mx0 = fmaxf(mx0, __shfl_xor_sync(0xffffffffu, mx0, 2));
            mx1 = fmaxf(mx1, __shfl_xor_sync(0xffffffffu, mx1, 1));
            mx1 = fmaxf(mx1, __shfl_xor_sync(0xffffffffu, mx1, 2));
            float mn0 = fmaxf(m0, mx0), mn1 = fmaxf(m1, mx1);
            float c0 = __expf(m0 - mn0), c1 = __expf(m1 - mn1);
            l0 *= c0; l1 *= c1;
#pragma unroll
            for (int nt = 0; nt < 16; nt++) {
                accO[nt][0] *= c0; accO[nt][1] *= c0;
                accO[nt][2] *= c1; accO[nt][3] *= c1;
            }
            float s0 = 0.f, s1 = 0.f;
            uint32_t pa0[16], pa1[16];
#pragma unroll
            for (int nt = 0; nt < 16; nt++) {
                float p0 = __expf(sA[nt][0] - mn0);
                float p1 = __expf(sA[nt][1] - mn0);
                float p2 = __expf(sA[nt][2] - mn1);
                float p3 = __expf(sA[nt][3] - mn1);
                s0 += p0 + p1; s1 += p2 + p3;
                pa0[nt] = packh2(p0, p1);
                pa1[nt] = packh2(p2, p3);
            }
            s0 += __shfl_xor_sync(0xffffffffu, s0, 1);
            s0 += __shfl_xor_sync(0xffffffffu, s0, 2);
            s1 += __shfl_xor_sync(0xffffffffu, s1, 1);
            s1 += __shfl_xor_sync(0xffffffffu, s1, 2);
            l0 += s0; l1 += s1; m0 = mn0; m1 = mn1;

#pragma unroll
            for (int kk = 0; kk < 8; kk++) {
                uint32_t a[4] = { pa0[2 * kk], pa1[2 * kk], pa0[2 * kk + 1], pa1[2 * kk + 1] };
#pragma unroll
                for (int np = 0; np < 8; np++) {
                    uint32_t bf[4];
                    ldsm4(bf, vBase + (uint32_t)(np * 16) * FROWB + (uint32_t)kk * 32);
                    mma16816(accO[2 * np],     a, bf[0], bf[1]);
                    mma16816(accO[2 * np + 1], a, bf[2], bf[3]);
                }
            }
        }

        // epilogue: O /= l, write half
        {
            float i0 = 1.f / l0, i1 = 1.f / l1;
            const int r = lane >> 2, cq = lane & 3;
            __half* Og = g_o + ((size_t)(b * LL + q0 + warp * 16)) * DIMM + h * HDIM;
#pragma unroll
            for (int nt = 0; nt < 16; nt++) {
                int col = nt * 8 + 2 * cq;
                *(__half2*)(Og + (size_t)r * DIMM + col) =
                    __floats2half2_rn(accO[nt][0] * i0, accO[nt][1] * i0);
                *(__half2*)(Og + (size_t)(r + 8) * DIMM + col) =
                    __floats2half2_rn(accO[nt][2] * i1, accO[nt][3] * i1);
            }
        }
        // next item's prologue CPA_WAIT/sync orders smem reuse
    }
}

// ============================================================
// convert helpers
// ============================================================
__global__ void cvt_h_kernel(const float* __restrict__ s, __half* __restrict__ d, size_t n4)
{
    size_t i = (size_t)blockIdx.x * blockDim.x + threadIdx.x;
    if (i < n4) {
        float4 v = ((const float4*)s)[i];
        ((__half2*)d)[2 * i]     = __floats2half2_rn(v.x, v.y);
        ((__half2*)d)[2 * i + 1] = __floats2half2_rn(v.z, v.w);
    }
}

__global__ void cvtT_kernel(const float* __restrict__ src, __half* __restrict__ dst,
                            int K, int N)
{
    __shared__ float tile[32][33];
    int k0 = blockIdx.y * 32, n0 = blockIdx.x * 32;
    int tx = threadIdx.x, ty = threadIdx.y;
#pragma unroll
    for (int i = 0; i < 32; i += 8)
        tile[ty + i][tx] = src[(size_t)(k0 + ty + i) * N + n0 + tx];
    __syncthreads();
#pragma unroll
    for (int i = 0; i < 32; i += 8)
        dst[(size_t)(n0 + ty + i) * K + k0 + tx] = __float2half_rn(tile[tx][ty + i]);
}

// V^T per head
__global__ void vtrans_kernel()
{
    __shared__ float tile[32][33];
    const int bh = blockIdx.z;
    const int b = bh / NHEADS, h = bh % NHEADS;
    const int k0 = blockIdx.x * 32, d0 = blockIdx.y * 32;
    const float* src = g_qkv + (size_t)b * LL * QKVDIM + 2 * DIMM + h * HDIM;
    __half* dst = g_vt + (size_t)bh * HDIM * LL;
    int tx = threadIdx.x, ty = threadIdx.y;
#pragma unroll
    for (int i = 0; i < 32; i += 8)
        tile[ty + i][tx] = src[(size_t)(k0 + ty + i) * QKVDIM + d0 + tx];
    __syncthreads();
#pragma unroll
    for (int i = 0; i < 32; i += 8)
        dst[(size_t)(d0 + ty + i) * LL + k0 + tx] = __float2half_rn(tile[tx][ty + i]);
}

// ============================================================
// RMSNorm + gain + RoPE -> half q (pre-scaled by SCALE), k
// ============================================================
__global__ __launch_bounds__(256) void rmsrope_kernel(
    const float* __restrict__ cosb, const float* __restrict__ sinb,
    const float* __restrict__ gq, const float* __restrict__ gk)
{
    const int t = blockIdx.x;
    const int tid = threadIdx.x;
    const float* base = g_qkv + (size_t)t * QKVDIM;

    float sq = 0.f, sk = 0.f;
    for (int i = tid; i < DIMM; i += 256) {
        float a = base[i];         sq = fmaf(a, a, sq);
        float b = base[DIMM + i];  sk = fmaf(b, b, sk);
    }
    __shared__ float r1[256], r2[256];
    r1[tid] = sq; r2[tid] = sk;
    __syncthreads();
    for (int s = 128; s > 0; s >>= 1) {
        if (tid < s) { r1[tid] += r1[tid + s]; r2[tid] += r2[tid + s]; }
        __syncthreads();
    }
    const float rq = rsqrtf(r1[0] / (float)DIMM + EPS);
    const float rk = rsqrtf(r2[0] / (float)DIMM + EPS);

    const int l = t & (LL - 1);
    const float* cl = cosb + (size_t)l * HDIM;
    const float* sl = sinb + (size_t)l * HDIM;
    __half* qo = g_q + (size_t)t * DIMM;
    __half* ko = g_k + (size_t)t * DIMM;

    for (int p = tid; p < DIMM / 2; p += 256) {
        int d = 2 * p;
        int hd = d & (HDIM - 1);
        float c = cl[hd];
        float s = sl[hd + 1];
        float x0 = base[d]     * rq * gq[d];
        float x1 = base[d + 1] * rq * gq[d + 1];
        *(__half2*)(qo + d) = __floats2half2_rn((x0 * c - x1 * s) * SCALE,
                                                (x0 * s + x1 * c) * SCALE);
        float y0 = base[DIMM + d]     * rk * gk[d];
        float y1 = base[DIMM + d + 1] * rk * gk[d + 1];
        *(__half2*)(ko + d) = __floats2half2_rn(y0 * c - y1 * s, y0 * s + y1 * c);
    }
}

// ============================================================
// launch
// ============================================================
extern "C" void kernel_launch(void* const* d_in, const int* in_sizes, int n_in,
                              void* d_out, int out_size)
{
    const float* x     = (const float*)d_in[0];
    const float* cosb  = (const float*)d_in[1];
    const float* sinb  = (const float*)d_in[2];
    const float* Wqkv  = (const float*)d_in[3];
    const float* bqkv  = (const float*)d_in[4];
    const float* gq    = (const float*)d_in[5];
    const float* gk    = (const float*)d_in[6];
    const float* Wout  = (const float*)d_in[7];
    const float* bout  = (const float*)d_in[8];
    float* out = (float*)d_out;

    void* p_qkv; cudaGetSymbolAddress(&p_qkv, g_qkv);
    void* p_o;   cudaGetSymbolAddress(&p_o,   g_o);
    void* p_wq;  cudaGetSymbolAddress(&p_wq,  g_wq);
    void* p_wo;  cudaGetSymbolAddress(&p_wo,  g_wo);
    void* p_x;   cudaGetSymbolAddress(&p_x,   g_x);

    cudaFuncSetAttribute(tc_gemm, cudaFuncAttributeMaxDynamicSharedMemorySize, GEMM_SMEM);
    cudaFuncSetAttribute(flash_kernel, cudaFuncAttributeMaxDynamicSharedMemorySize, FLASH_SMEM);

    // 0) weight transpose + fp16 rounding; activation rounding
    cvtT_kernel<<<dim3(QKVDIM / 32, DIMM / 32), dim3(32, 8)>>>(Wqkv, (__half*)p_wq, DIMM, QKVDIM);
    cvtT_kernel<<<dim3(DIMM / 32,  DIMM / 32), dim3(32, 8)>>>(Wout, (__half*)p_wo, DIMM, DIMM);
    {
        size_t n4 = (size_t)TOKENS * DIMM / 4;
        cvt_h_kernel<<<(unsigned)((n4 + 255) / 256), 256>>>(x, (__half*)p_x, n4);
    }

    // 1) QKV projection (non-persistent, M tiles on x)
    tc_gemm<<<dim3(TOKENS / 128, QKVDIM / 128, 1), 256, GEMM_SMEM>>>(
        (const __half*)p_x, (const __half*)p_wq, bqkv, p_qkv,
        0, 0, 0, DIMM, DIMM, QKVDIM, DIMM, 1.f, 0);

    // 2) RMSNorm + RoPE (half out, q pre-scaled), V transpose (half out)
    rmsrope_kernel<<<TOKENS, 256>>>(cosb, sinb, gq, gk);
    vtrans_kernel<<<dim3(LL / 32, HDIM / 32, BB * NHEADS), dim3(32, 8)>>>();

    // 3) fused attention: persistent over 640 items
    flash_kernel<<<FLASH_GRID, 256, FLASH_SMEM>>>();

    // 4) out projection (non-persistent)
    tc_gemm<<<dim3(TOKENS / 128, DIMM / 128, 1), 256, GEMM_SMEM>>>(
        (const __half*)p_o, (const __half*)p_wo, bout, out,
        0, 0, 0, DIMM, DIMM, DIMM, DIMM, 1.f, 0);
}

// round 13
// speedup vs baseline: 1.1736x; 1.0210x over previous
#include <cuda_runtime.h>
#include <cuda_fp16.h>
#include <math.h>
#include <stdint.h>

// Problem constants
#define DIMM 5120
#define NHEADS 40
#define HDIM 128
#define BB 2
#define LL 1024
#define TOKENS (BB*LL)          // 2048
#define QKVDIM (3*DIMM)         // 15360
#define SCALE 0.08838834764831845f
#define EPS 1e-6f

// -------- scratch (static device globals; no runtime allocation) --------
__device__ __half g_qkvh[(size_t)TOKENS * QKVDIM];          // 62.9 MB half
__device__ __half g_q[(size_t)TOKENS * DIMM];               // scaled by SCALE
__device__ __half g_k[(size_t)TOKENS * DIMM];
__device__ __half g_o[(size_t)TOKENS * DIMM];
__device__ __half g_wq[(size_t)QKVDIM * DIMM];              // W_qkv^T [N,K]
__device__ __half g_wo[(size_t)DIMM * DIMM];                // W_out^T [N,K]
__device__ __half g_x[(size_t)TOKENS * DIMM];               // x, half

// ============================================================
// helpers
// ============================================================
__device__ __forceinline__ uint32_t smem_u32(const void* p) {
    uint32_t a;
    asm("{ .reg .u64 t; cvta.to.shared.u64 t, %1; cvt.u32.u64 %0, t; }" : "=r"(a) : "l"(p));
    return a;
}
__device__ __forceinline__ void cpa16(uint32_t dst, const void* src) {
    asm volatile("cp.async.cg.shared.global [%0], [%1], 16;" :: "r"(dst), "l"(src));
}
#define CPA_COMMIT() asm volatile("cp.async.commit_group;" ::: "memory")
#define CPA_WAIT1()  asm volatile("cp.async.wait_group 1;" ::: "memory")
#define CPA_WAIT0()  asm volatile("cp.async.wait_group 0;" ::: "memory")

// fp16 m16n8k16, f32 accum
__device__ __forceinline__ void mma16816(float* d, const uint32_t* a, uint32_t b0, uint32_t b1) {
    asm volatile(
        "mma.sync.aligned.m16n8k16.row.col.f32.f16.f16.f32 "
        "{%0,%1,%2,%3}, {%4,%5,%6,%7}, {%8,%9}, {%0,%1,%2,%3};"
        : "+f"(d[0]), "+f"(d[1]), "+f"(d[2]), "+f"(d[3])
        : "r"(a[0]), "r"(a[1]), "r"(a[2]), "r"(a[3]), "r"(b0), "r"(b1));
}
__device__ __forceinline__ void ldsm4(uint32_t* r, uint32_t addr) {
    asm volatile("ldmatrix.sync.aligned.m8n8.x4.shared.b16 {%0,%1,%2,%3}, [%4];"
        : "=r"(r[0]), "=r"(r[1]), "=r"(r[2]), "=r"(r[3]) : "r"(addr));
}
__device__ __forceinline__ void ldsm4t(uint32_t* r, uint32_t addr) {
    asm volatile("ldmatrix.sync.aligned.m8n8.x4.trans.shared.b16 {%0,%1,%2,%3}, [%4];"
        : "=r"(r[0]), "=r"(r[1]), "=r"(r[2]), "=r"(r[3]) : "r"(addr));
}
__device__ __forceinline__ uint32_t packh2(float x, float y) {
    __half2 h = __floats2half2_rn(x, y);
    return *(uint32_t*)&h;
}

// ============================================================
// fp16 mma.sync GEMM (R8-exact):
//   C[m,n] = alpha * A[m,:K] * Bt[n,:K]^T (+ bias[n])
// CTA tile 128x128, 256 threads, 8 warps 2(M)x4(N), warp tile 64x32.
// K-chunk 64, 3-stage cp.async, 2 CTAs/SM.
// ============================================================
#define KC 64
#define ROWB 144
#define TILE_B (128 * ROWB)
#define STAGE_B (2 * TILE_B)
#define NSTG 3
#define GEMM_SMEM (NSTG * STAGE_B)          // 110592 B

__global__ __launch_bounds__(256) void tc_gemm(
    const __half* __restrict__ A, const __half* __restrict__ Bt,
    const float* __restrict__ bias, void* __restrict__ Cv,
    int lda, int ldb, int ldc, int K, float alpha, int store_half)
{
    extern __shared__ char sm[];
    const uint32_t sb = smem_u32(sm);

    const int tid  = threadIdx.x;
    const int warp = tid >> 5;
    const int lane = tid & 31;
    const int wm = warp >> 2;
    const int wn = warp & 3;
    const int m0 = blockIdx.x * 128;
    const int n0 = blockIdx.y * 128;

    const uint32_t aOff = (uint32_t)(lane & 15) * ROWB + (uint32_t)(lane >> 4) * 16;
    const uint32_t bOff = (uint32_t)((lane & 7) + ((lane >> 4) & 1) * 8) * ROWB
                        + (uint32_t)((lane >> 3) & 1) * 16;

    float acc[4][4][4];
#pragma unroll
    for (int mt = 0; mt < 4; mt++)
#pragma unroll
        for (int nt = 0; nt < 4; nt++)
#pragma unroll
            for (int r = 0; r < 4; r++) acc[mt][nt][r] = 0.f;

    const int nch = K / KC;

    auto load_chunk = [&](int st, int kc) {
        uint32_t base = sb + (uint32_t)st * STAGE_B;
#pragma unroll
        for (int i = 0; i < 4; i++) {
            int op = tid + i * 256;
            int row = op >> 3, g = op & 7;
            uint32_t off = (uint32_t)row * ROWB + (uint32_t)g * 16;
            cpa16(base + off,
                  (const char*)A + ((size_t)(m0 + row) * lda + kc + g * 8) * 2);
            cpa16(base + TILE_B + off,
                  (const char*)Bt + ((size_t)(n0 + row) * ldb + kc + g * 8) * 2);
        }
    };

    load_chunk(0, 0);       CPA_COMMIT();
    if (nch > 1) { load_chunk(1, KC); CPA_COMMIT(); }

    for (int c = 0; c < nch; c++) {
        const int st = c % NSTG;
        if (c + 1 < nch) { CPA_WAIT1(); } else { CPA_WAIT0(); }
        __syncthreads();
        if (c + 2 < nch) { load_chunk((c + 2) % NSTG, (c + 2) * KC); CPA_COMMIT(); }

        const uint32_t aBase = sb + (uint32_t)st * STAGE_B
                             + (uint32_t)(wm * 64) * ROWB + aOff;
        const uint32_t bBase = sb + (uint32_t)st * STAGE_B + TILE_B
                             + (uint32_t)(wn * 32) * ROWB + bOff;

#pragma unroll
        for (int s = 0; s < 4; s++) {
            const uint32_t kb = (uint32_t)s * 32;
            uint32_t af[4][4];
#pragma unroll
            for (int mt = 0; mt < 4; mt++)
                ldsm4(af[mt], aBase + (uint32_t)(mt * 16) * ROWB + kb);
            uint32_t bf[2][4];
#pragma unroll
            for (int np = 0; np < 2; np++)
                ldsm4(bf[np], bBase + (uint32_t)(np * 16) * ROWB + kb);
#pragma unroll
            for (int mt = 0; mt < 4; mt++)
#pragma unroll
                for (int nt = 0; nt < 4; nt++)
                    mma16816(acc[mt][nt], af[mt],
                             bf[nt >> 1][(nt & 1) * 2], bf[nt >> 1][(nt & 1) * 2 + 1]);
        }
    }

    {
        const int r = lane >> 2, cq = lane & 3;
#pragma unroll
        for (int mt = 0; mt < 4; mt++) {
            int row = m0 + wm * 64 + mt * 16 + r;
#pragma unroll
            for (int nt = 0; nt < 4; nt++) {
                int col = n0 + wn * 32 + nt * 8 + 2 * cq;
                float bvx = 0.f, bvy = 0.f;
                if (bias) { float2 bv = *(const float2*)(bias + col); bvx = bv.x; bvy = bv.y; }
                float o0x = fmaf(acc[mt][nt][0], alpha, bvx);
                float o0y = fmaf(acc[mt][nt][1], alpha, bvy);
                float o1x = fmaf(acc[mt][nt][2], alpha, bvx);
                float o1y = fmaf(acc[mt][nt][3], alpha, bvy);
                if (store_half) {
                    __half* C = (__half*)Cv;
                    *(__half2*)(C + (size_t)row * ldc + col) = __floats2half2_rn(o0x, o0y);
                    *(__half2*)(C + (size_t)(row + 8) * ldc + col) = __floats2half2_rn(o1x, o1y);
                } else {
                    float* C = (float*)Cv;
                    *(float2*)(C + (size_t)row * ldc + col) = make_float2(o0x, o0y);
                    *(float2*)(C + (size_t)(row + 8) * ldc + col) = make_float2(o1x, o1y);
                }
            }
        }
    }
}

// ============================================================
// Persistent flash attention: work item = (q-tile, bh).
// CTA = 128 q rows x one (b,h); 8 warps x 16 rows; online softmax.
// V loaded DIRECTLY from g_qkvh [seq][d] via ldmatrix.trans.
// Grid = 148 persistent CTAs over 640 items.
// ============================================================
#define FROWB 272
#define FTILE_B (128 * FROWB)               // 34816
#define FLASH_SMEM (5 * FTILE_B)            // 174080: Q + 2x(K+V)
#define FLASH_GRID 148
#define FLASH_ITEMS (BB * NHEADS * (LL / 128))   // 640

__global__ __launch_bounds__(256, 1) void flash_kernel()
{
    extern __shared__ char sm[];
    const uint32_t sb = smem_u32(sm);
    const int tid = threadIdx.x, warp = tid >> 5, lane = tid & 31;

    const uint32_t aOff = (uint32_t)(lane & 15) * FROWB + (uint32_t)(lane >> 4) * 16;
    const uint32_t bOff = (uint32_t)((lane & 7) + ((lane >> 4) & 1) * 8) * FROWB
                        + (uint32_t)((lane >> 3) & 1) * 16;
    // trans-ldsm offsets for V [seq(k)][d(n)] tiles:
    // rows (l&7)+8*((l>>3)&1), col-half (l>>4)*16B
    const uint32_t vOffT = (uint32_t)((lane & 7) + ((lane >> 3) & 1) * 8) * FROWB
                         + (uint32_t)(lane >> 4) * 16;

    for (int it = blockIdx.x; it < FLASH_ITEMS; it += gridDim.x) {
        const int q0 = (it & 7) * 128;          // 8 q-tiles fastest -> K/V L2 reuse
        const int bh = it >> 3;
        const int b = bh / NHEADS, h = bh % NHEADS;

        const char* Qg = (const char*)(g_q + ((size_t)(b * LL + q0)) * DIMM + h * HDIM);
        const char* Kg = (const char*)(g_k + ((size_t)(b * LL)) * DIMM + h * HDIM);
        const char* Vg = (const char*)(g_qkvh + (size_t)(b * LL) * QKVDIM + 2 * DIMM + h * HDIM);

        auto load_kv = [&](int st, int j) {
            uint32_t kb = sb + FTILE_B + (uint32_t)st * (2 * FTILE_B);
            uint32_t vb = kb + FTILE_B;
#pragma unroll
            for (int i = 0; i < 8; i++) {
                int op = tid + i * 256;
                int row = op >> 4, g = op & 15;
                uint32_t off = (uint32_t)row * FROWB + (uint32_t)g * 16;
                cpa16(kb + off, Kg + ((size_t)(j * 128 + row) * DIMM) * 2 + g * 16);
                cpa16(vb + off, Vg + ((size_t)(j * 128 + row) * QKVDIM) * 2 + g * 16);
            }
        };

        // prologue: Q tile + KV block 0
        {
#pragma unroll
            for (int i = 0; i < 8; i++) {
                int op = tid + i * 256;
                int row = op >> 4, g = op & 15;
                cpa16(sb + (uint32_t)row * FROWB + (uint32_t)g * 16,
                      Qg + (size_t)row * DIMM * 2 + g * 16);
            }
            CPA_COMMIT();
            load_kv(0, 0); CPA_COMMIT();
            CPA_WAIT1();            // Q resident
            __syncthreads();
        }

        uint32_t aq[8][4];
        {
            uint32_t qBase = sb + (uint32_t)(warp * 16) * FROWB + aOff;
#pragma unroll
            for (int kk = 0; kk < 8; kk++)
                ldsm4(aq[kk], qBase + (uint32_t)kk * 32);
        }

        float accO[16][4];
#pragma unroll
        for (int nt = 0; nt < 16; nt++)
#pragma unroll
            for (int r = 0; r < 4; r++) accO[nt][r] = 0.f;
        float m0 = -1e30f, m1 = -1e30f, l0 = 0.f, l1 = 0.f;

        for (int j = 0; j < 8; j++) {
            const int st = j & 1;
            CPA_WAIT0();
            __syncthreads();
            if (j + 1 < 8) { load_kv((j + 1) & 1, j + 1); CPA_COMMIT(); }

            const uint32_t kBase = sb + FTILE_B + (uint32_t)st * (2 * FTILE_B) + bOff;
            const uint32_t vBase = sb + FTILE_B + (uint32_t)st * (2 * FTILE_B) + FTILE_B + vOffT;

            float sA[16][4];
#pragma unroll
            for (int nt = 0; nt < 16; nt++)
#pragma unroll
                for (int r = 0; r < 4; r++) sA[nt][r] = 0.f;
#pragma unroll
            for (int kk = 0; kk < 8; kk++) {
#pragma unroll
                for (int np = 0; np < 8; np++) {
                    uint32_t bf[4];
                    ldsm4(bf, kBase + (uint32_t)(np * 16) * FROWB + (uint32_t)kk * 32);
                    mma16816(sA[2 * np],     aq[kk], bf[0], bf[1]);
                    mma16816(sA[2 * np + 1], aq[kk], bf[2], bf[3]);
                }
            }

            float mx0 = -1e30f, mx1 = -1e30f;
#pragma unroll
            for (int nt = 0; nt < 16; nt++) {
                mx0 = fmaxf(mx0, fmaxf(sA[nt][0], sA[nt][1]));
                mx1 = fmaxf(mx1, fmaxf(sA[nt][2], sA[nt][3]));
            }
            mx0 = fmaxf(mx0, __shfl_xor_sync(0xffffffffu, mx0, 1));
            mx0 = fmaxf(mx0, __shfl_xor_sync(0xffffffffu, mx0, 2));
            mx1 = fmaxf(mx1, __shfl_xor_sync(0xffffffffu, mx1, 1));
            mx1 = fmaxf(mx1, __shfl_xor_sync(0xffffffffu, mx1, 2));
            float mn0 = fmaxf(m0, mx0), mn1 = fmaxf(m1, mx1);
            float c0 = __expf(m0 - mn0), c1 = __expf(m1 - mn1);
            l0 *= c0; l1 *= c1;
#pragma unroll
            for (int nt = 0; nt < 16; nt++) {
                accO[nt][0] *= c0; accO[nt][1] *= c0;
                accO[nt][2] *= c1; accO[nt][3] *= c1;
            }
            float s0 = 0.f, s1 = 0.f;
            uint32_t pa0[16], pa1[16];
#pragma unroll
            for (int nt = 0; nt < 16; nt++) {
                float p0 = __expf(sA[nt][0] - mn0);
                float p1 = __expf(sA[nt][1] - mn0);
                float p2 = __expf(sA[nt][2] - mn1);
                float p3 = __expf(sA[nt][3] - mn1);
                s0 += p0 + p1; s1 += p2 + p3;
                pa0[nt] = packh2(p0, p1);
                pa1[nt] = packh2(p2, p3);
            }
            s0 += __shfl_xor_sync(0xffffffffu, s0, 1);
            s0 += __shfl_xor_sync(0xffffffffu, s0, 2);
            s1 += __shfl_xor_sync(0xffffffffu, s1, 1);
            s1 += __shfl_xor_sync(0xffffffffu, s1, 2);
            l0 += s0; l1 += s1; m0 = mn0; m1 = mn1;

            // O += P V : V tile is [seq(k)][d(n)], fragments via trans-ldsm
#pragma unroll
            for (int kk = 0; kk < 8; kk++) {
                uint32_t a[4] = { pa0[2 * kk], pa1[2 * kk], pa0[2 * kk + 1], pa1[2 * kk + 1] };
#pragma unroll
                for (int np = 0; np < 8; np++) {
                    uint32_t bf[4];
                    ldsm4t(bf, vBase + (uint32_t)(kk * 16) * FROWB + (uint32_t)np * 32);
                    mma16816(accO[2 * np],     a, bf[0], bf[1]);
                    mma16816(accO[2 * np + 1], a, bf[2], bf[3]);
                }
            }
        }

        // epilogue: O /= l, write half
        {
            float i0 = 1.f / l0, i1 = 1.f / l1;
            const int r = lane >> 2, cq = lane & 3;
            __half* Og = g_o + ((size_t)(b * LL + q0 + warp * 16)) * DIMM + h * HDIM;
#pragma unroll
            for (int nt = 0; nt < 16; nt++) {
                int col = nt * 8 + 2 * cq;
                *(__half2*)(Og + (size_t)r * DIMM + col) =
                    __floats2half2_rn(accO[nt][0] * i0, accO[nt][1] * i0);
                *(__half2*)(Og + (size_t)(r + 8) * DIMM + col) =
                    __floats2half2_rn(accO[nt][2] * i1, accO[nt][3] * i1);
            }
        }
    }
}

// ============================================================
// convert helpers
// ============================================================
__global__ void cvt_h_kernel(const float* __restrict__ s, __half* __restrict__ d, size_t n4)
{
    size_t i = (size_t)blockIdx.x * blockDim.x + threadIdx.x;
    if (i < n4) {
        float4 v = ((const float4*)s)[i];
        ((__half2*)d)[2 * i]     = __floats2half2_rn(v.x, v.y);
        ((__half2*)d)[2 * i + 1] = __floats2half2_rn(v.z, v.w);
    }
}

__global__ void cvtT_kernel(const float* __restrict__ src, __half* __restrict__ dst,
                            int K, int N)
{
    __shared__ float tile[32][33];
    int k0 = blockIdx.y * 32, n0 = blockIdx.x * 32;
    int tx = threadIdx.x, ty = threadIdx.y;
#pragma unroll
    for (int i = 0; i < 32; i += 8)
        tile[ty + i][tx] = src[(size_t)(k0 + ty + i) * N + n0 + tx];
    __syncthreads();
#pragma unroll
    for (int i = 0; i < 32; i += 8)
        dst[(size_t)(n0 + ty + i) * K + k0 + tx] = __float2half_rn(tile[tx][ty + i]);
}

// ============================================================
// RMSNorm + gain + RoPE -> half q (pre-scaled by SCALE), k
// reads half qkv
// ============================================================
__global__ __launch_bounds__(256) void rmsrope_kernel(
    const float* __restrict__ cosb, const float* __restrict__ sinb,
    const float* __restrict__ gq, const float* __restrict__ gk)
{
    const int t = blockIdx.x;
    const int tid = threadIdx.x;
    const __half2* baseq = (const __half2*)(g_qkvh + (size_t)t * QKVDIM);
    const __half2* basek = (const __half2*)(g_qkvh + (size_t)t * QKVDIM + DIMM);

    float sq = 0.f, sk = 0.f;
    for (int p = tid; p < DIMM / 2; p += 256) {
        float2 a = __half22float2(baseq[p]);
        float2 b = __half22float2(basek[p]);
        sq = fmaf(a.x, a.x, fmaf(a.y, a.y, sq));
        sk = fmaf(b.x, b.x, fmaf(b.y, b.y, sk));
    }
    __shared__ float r1[256], r2[256];
    r1[tid] = sq; r2[tid] = sk;
    __syncthreads();
    for (int s = 128; s > 0; s >>= 1) {
        if (tid < s) { r1[tid] += r1[tid + s]; r2[tid] += r2[tid + s]; }
        __syncthreads();
    }
    const float rq = rsqrtf(r1[0] / (float)DIMM + EPS);
    const float rk = rsqrtf(r2[0] / (float)DIMM + EPS);

    const int l = t & (LL - 1);
    const float* cl = cosb + (size_t)l * HDIM;
    const float* sl = sinb + (size_t)l * HDIM;
    __half* qo = g_q + (size_t)t * DIMM;
    __half* ko = g_k + (size_t)t * DIMM;

    for (int p = tid; p < DIMM / 2; p += 256) {
        int d = 2 * p;
        int hd = d & (HDIM - 1);
        float c = cl[hd];
        float s = sl[hd + 1];
        float2 av = __half22float2(baseq[p]);
        float2 bv = __half22float2(basek[p]);
        float x0 = av.x * rq * gq[d];
        float x1 = av.y * rq * gq[d + 1];
        *(__half2*)(qo + d) = __floats2half2_rn((x0 * c - x1 * s) * SCALE,
                                                (x0 * s + x1 * c) * SCALE);
        float y0 = bv.x * rk * gk[d];
        float y1 = bv.y * rk * gk[d + 1];
        *(__half2*)(ko + d) = __floats2half2_rn(y0 * c - y1 * s, y0 * s + y1 * c);
    }
}

// ============================================================
// launch
// ============================================================
extern "C" void kernel_launch(void* const* d_in, const int* in_sizes, int n_in,
                              void* d_out, int out_size)
{
    const float* x     = (const float*)d_in[0];
    const float* cosb  = (const float*)d_in[1];
    const float* sinb  = (const float*)d_in[2];
    const float* Wqkv  = (const float*)d_in[3];
    const float* bqkv  = (const float*)d_in[4];
    const float* gq    = (const float*)d_in[5];
    const float* gk    = (const float*)d_in[6];
    const float* Wout  = (const float*)d_in[7];
    const float* bout  = (const float*)d_in[8];
    float* out = (float*)d_out;

    void* p_qkvh; cudaGetSymbolAddress(&p_qkvh, g_qkvh);
    void* p_o;    cudaGetSymbolAddress(&p_o,    g_o);
    void* p_wq;   cudaGetSymbolAddress(&p_wq,   g_wq);
    void* p_wo;   cudaGetSymbolAddress(&p_wo,   g_wo);
    void* p_x;    cudaGetSymbolAddress(&p_x,    g_x);

    cudaFuncSetAttribute(tc_gemm, cudaFuncAttributeMaxDynamicSharedMemorySize, GEMM_SMEM);
    cudaFuncSetAttribute(flash_kernel, cudaFuncAttributeMaxDynamicSharedMemorySize, FLASH_SMEM);

    // 0) weight transpose + fp16 rounding; activation rounding
    cvtT_kernel<<<dim3(QKVDIM / 32, DIMM / 32), dim3(32, 8)>>>(Wqkv, (__half*)p_wq, DIMM, QKVDIM);
    cvtT_kernel<<<dim3(DIMM / 32,  DIMM / 32), dim3(32, 8)>>>(Wout, (__half*)p_wo, DIMM, DIMM);
    {
        size_t n4 = (size_t)TOKENS * DIMM / 4;
        cvt_h_kernel<<<(unsigned)((n4 + 255) / 256), 256>>>(x, (__half*)p_x, n4);
    }

    // 1) QKV projection -> half directly
    tc_gemm<<<dim3(TOKENS / 128, QKVDIM / 128, 1), 256, GEMM_SMEM>>>(
        (const __half*)p_x, (const __half*)p_wq, bqkv, p_qkvh,
        DIMM, DIMM, QKVDIM, DIMM, 1.f, 1);

    // 2) RMSNorm + RoPE (half in/out, q pre-scaled)
    rmsrope_kernel<<<TOKENS, 256>>>(cosb, sinb, gq, gk);

    // 3) fused attention: persistent; V read straight from g_qkvh (trans-ldsm)
    flash_kernel<<<FLASH_GRID, 256, FLASH_SMEM>>>();

    // 4) out projection (f32 out to d_out)
    tc_gemm<<<dim3(TOKENS / 128, DIMM / 128, 1), 256, GEMM_SMEM>>>(
        (const __half*)p_o, (const __half*)p_wo, bout, out,
        DIMM, DIMM, DIMM, DIMM, 1.f, 0);
}

// round 15
// speedup vs baseline: 1.1761x; 1.0021x over previous
#include <cuda_runtime.h>
#include <cuda_fp16.h>
#include <math.h>
#include <stdint.h>

// Problem constants
#define DIMM 5120
#define NHEADS 40
#define HDIM 128
#define BB 2
#define LL 1024
#define TOKENS (BB*LL)          // 2048
#define QKVDIM (3*DIMM)         // 15360
#define SCALE 0.08838834764831845f
#define EPS 1e-6f

// -------- scratch (static device globals; no runtime allocation) --------
__device__ __half g_qkvh[(size_t)TOKENS * QKVDIM];          // 62.9 MB half
__device__ __half g_q[(size_t)TOKENS * DIMM];               // scaled by SCALE
__device__ __half g_k[(size_t)TOKENS * DIMM];
__device__ __half g_o[(size_t)TOKENS * DIMM];
__device__ __half g_wq[(size_t)QKVDIM * DIMM];              // W_qkv^T [N,K]
__device__ __half g_wo[(size_t)DIMM * DIMM];                // W_out^T [N,K]
__device__ __half g_x[(size_t)TOKENS * DIMM];               // x, half

// ============================================================
// helpers
// ============================================================
__device__ __forceinline__ uint32_t smem_u32(const void* p) {
    uint32_t a;
    asm("{ .reg .u64 t; cvta.to.shared.u64 t, %1; cvt.u32.u64 %0, t; }" : "=r"(a) : "l"(p));
    return a;
}
__device__ __forceinline__ void cpa16(uint32_t dst, const void* src) {
    asm volatile("cp.async.cg.shared.global [%0], [%1], 16;" :: "r"(dst), "l"(src));
}
#define CPA_COMMIT() asm volatile("cp.async.commit_group;" ::: "memory")
#define CPA_WAIT1()  asm volatile("cp.async.wait_group 1;" ::: "memory")
#define CPA_WAIT0()  asm volatile("cp.async.wait_group 0;" ::: "memory")

// fp16 m16n8k16, f32 accum
__device__ __forceinline__ void mma16816(float* d, const uint32_t* a, uint32_t b0, uint32_t b1) {
    asm volatile(
        "mma.sync.aligned.m16n8k16.row.col.f32.f16.f16.f32 "
        "{%0,%1,%2,%3}, {%4,%5,%6,%7}, {%8,%9}, {%0,%1,%2,%3};"
        : "+f"(d[0]), "+f"(d[1]), "+f"(d[2]), "+f"(d[3])
        : "r"(a[0]), "r"(a[1]), "r"(a[2]), "r"(a[3]), "r"(b0), "r"(b1));
}
__device__ __forceinline__ void ldsm4(uint32_t* r, uint32_t addr) {
    asm volatile("ldmatrix.sync.aligned.m8n8.x4.shared.b16 {%0,%1,%2,%3}, [%4];"
        : "=r"(r[0]), "=r"(r[1]), "=r"(r[2]), "=r"(r[3]) : "r"(addr));
}
__device__ __forceinline__ void ldsm4t(uint32_t* r, uint32_t addr) {
    asm volatile("ldmatrix.sync.aligned.m8n8.x4.trans.shared.b16 {%0,%1,%2,%3}, [%4];"
        : "=r"(r[0]), "=r"(r[1]), "=r"(r[2]), "=r"(r[3]) : "r"(addr));
}
__device__ __forceinline__ uint32_t packh2(float x, float y) {
    __half2 h = __floats2half2_rn(x, y);
    return *(uint32_t*)&h;
}

// ============================================================
// fp16 mma.sync GEMM (R8-exact):
//   C[m,n] = alpha * A[m,:K] * Bt[n,:K]^T (+ bias[n])
// CTA tile 128x128, 256 threads, 8 warps 2(M)x4(N), warp tile 64x32.
// K-chunk 64, 3-stage cp.async, 2 CTAs/SM.
// ============================================================
#define KC 64
#define ROWB 144
#define TILE_B (128 * ROWB)
#define STAGE_B (2 * TILE_B)
#define NSTG 3
#define GEMM_SMEM (NSTG * STAGE_B)          // 110592 B

__global__ __launch_bounds__(256) void tc_gemm(
    const __half* __restrict__ A, const __half* __restrict__ Bt,
    const float* __restrict__ bias, void* __restrict__ Cv,
    int lda, int ldb, int ldc, int K, float alpha, int store_half)
{
    extern __shared__ char sm[];
    const uint32_t sb = smem_u32(sm);

    const int tid  = threadIdx.x;
    const int warp = tid >> 5;
    const int lane = tid & 31;
    const int wm = warp >> 2;
    const int wn = warp & 3;
    const int m0 = blockIdx.x * 128;
    const int n0 = blockIdx.y * 128;

    const uint32_t aOff = (uint32_t)(lane & 15) * ROWB + (uint32_t)(lane >> 4) * 16;
    const uint32_t bOff = (uint32_t)((lane & 7) + ((lane >> 4) & 1) * 8) * ROWB
                        + (uint32_t)((lane >> 3) & 1) * 16;

    float acc[4][4][4];
#pragma unroll
    for (int mt = 0; mt < 4; mt++)
#pragma unroll
        for (int nt = 0; nt < 4; nt++)
#pragma unroll
            for (int r = 0; r < 4; r++) acc[mt][nt][r] = 0.f;

    const int nch = K / KC;

    auto load_chunk = [&](int st, int kc) {
        uint32_t base = sb + (uint32_t)st * STAGE_B;
#pragma unroll
        for (int i = 0; i < 4; i++) {
            int op = tid + i * 256;
            int row = op >> 3, g = op & 7;
            uint32_t off = (uint32_t)row * ROWB + (uint32_t)g * 16;
            cpa16(base + off,
                  (const char*)A + ((size_t)(m0 + row) * lda + kc + g * 8) * 2);
            cpa16(base + TILE_B + off,
                  (const char*)Bt + ((size_t)(n0 + row) * ldb + kc + g * 8) * 2);
        }
    };

    load_chunk(0, 0);       CPA_COMMIT();
    if (nch > 1) { load_chunk(1, KC); CPA_COMMIT(); }

    for (int c = 0; c < nch; c++) {
        const int st = c % NSTG;
        if (c + 1 < nch) { CPA_WAIT1(); } else { CPA_WAIT0(); }
        __syncthreads();
        if (c + 2 < nch) { load_chunk((c + 2) % NSTG, (c + 2) * KC); CPA_COMMIT(); }

        const uint32_t aBase = sb + (uint32_t)st * STAGE_B
                             + (uint32_t)(wm * 64) * ROWB + aOff;
        const uint32_t bBase = sb + (uint32_t)st * STAGE_B + TILE_B
                             + (uint32_t)(wn * 32) * ROWB + bOff;

#pragma unroll
        for (int s = 0; s < 4; s++) {
            const uint32_t kb = (uint32_t)s * 32;
            uint32_t af[4][4];
#pragma unroll
            for (int mt = 0; mt < 4; mt++)
                ldsm4(af[mt], aBase + (uint32_t)(mt * 16) * ROWB + kb);
            uint32_t bf[2][4];
#pragma unroll
            for (int np = 0; np < 2; np++)
                ldsm4(bf[np], bBase + (uint32_t)(np * 16) * ROWB + kb);
#pragma unroll
            for (int mt = 0; mt < 4; mt++)
#pragma unroll
                for (int nt = 0; nt < 4; nt++)
                    mma16816(acc[mt][nt], af[mt],
                             bf[nt >> 1][(nt & 1) * 2], bf[nt >> 1][(nt & 1) * 2 + 1]);
        }
    }

    {
        const int r = lane >> 2, cq = lane & 3;
#pragma unroll
        for (int mt = 0; mt < 4; mt++) {
            int row = m0 + wm * 64 + mt * 16 + r;
#pragma unroll
            for (int nt = 0; nt < 4; nt++) {
                int col = n0 + wn * 32 + nt * 8 + 2 * cq;
                float bvx = 0.f, bvy = 0.f;
                if (bias) { float2 bv = *(const float2*)(bias + col); bvx = bv.x; bvy = bv.y; }
                float o0x = fmaf(acc[mt][nt][0], alpha, bvx);
                float o0y = fmaf(acc[mt][nt][1], alpha, bvy);
                float o1x = fmaf(acc[mt][nt][2], alpha, bvx);
                float o1y = fmaf(acc[mt][nt][3], alpha, bvy);
                if (store_half) {
                    __half* C = (__half*)Cv;
                    *(__half2*)(C + (size_t)row * ldc + col) = __floats2half2_rn(o0x, o0y);
                    *(__half2*)(C + (size_t)(row + 8) * ldc + col) = __floats2half2_rn(o1x, o1y);
                } else {
                    float* C = (float*)Cv;
                    *(float2*)(C + (size_t)row * ldc + col) = make_float2(o0x, o0y);
                    *(float2*)(C + (size_t)(row + 8) * ldc + col) = make_float2(o1x, o1y);
                }
            }
        }
    }
}

// ============================================================
// Persistent flash attention (R13): work item = (q-tile, bh).
// V loaded directly from g_qkvh [seq][d] via ldmatrix.trans.
// ============================================================
#define FROWB 272
#define FTILE_B (128 * FROWB)               // 34816
#define FLASH_SMEM (5 * FTILE_B)            // 174080: Q + 2x(K+V)
#define FLASH_GRID 148
#define FLASH_ITEMS (BB * NHEADS * (LL / 128))   // 640

__global__ __launch_bounds__(256, 1) void flash_kernel()
{
    extern __shared__ char sm[];
    const uint32_t sb = smem_u32(sm);
    const int tid = threadIdx.x, warp = tid >> 5, lane = tid & 31;

    const uint32_t aOff = (uint32_t)(lane & 15) * FROWB + (uint32_t)(lane >> 4) * 16;
    const uint32_t bOff = (uint32_t)((lane & 7) + ((lane >> 4) & 1) * 8) * FROWB
                        + (uint32_t)((lane >> 3) & 1) * 16;
    const uint32_t vOffT = (uint32_t)((lane & 7) + ((lane >> 3) & 1) * 8) * FROWB
                         + (uint32_t)(lane >> 4) * 16;

    for (int it = blockIdx.x; it < FLASH_ITEMS; it += gridDim.x) {
        const int q0 = (it & 7) * 128;
        const int bh = it >> 3;
        const int b = bh / NHEADS, h = bh % NHEADS;

        const char* Qg = (const char*)(g_q + ((size_t)(b * LL + q0)) * DIMM + h * HDIM);
        const char* Kg = (const char*)(g_k + ((size_t)(b * LL)) * DIMM + h * HDIM);
        const char* Vg = (const char*)(g_qkvh + (size_t)(b * LL) * QKVDIM + 2 * DIMM + h * HDIM);

        auto load_kv = [&](int st, int j) {
            uint32_t kb = sb + FTILE_B + (uint32_t)st * (2 * FTILE_B);
            uint32_t vb = kb + FTILE_B;
#pragma unroll
            for (int i = 0; i < 8; i++) {
                int op = tid + i * 256;
                int row = op >> 4, g = op & 15;
                uint32_t off = (uint32_t)row * FROWB + (uint32_t)g * 16;
                cpa16(kb + off, Kg + ((size_t)(j * 128 + row) * DIMM) * 2 + g * 16);
                cpa16(vb + off, Vg + ((size_t)(j * 128 + row) * QKVDIM) * 2 + g * 16);
            }
        };

        {
#pragma unroll
            for (int i = 0; i < 8; i++) {
                int op = tid + i * 256;
                int row = op >> 4, g = op & 15;
                cpa16(sb + (uint32_t)row * FROWB + (uint32_t)g * 16,
                      Qg + (size_t)row * DIMM * 2 + g * 16);
            }
            CPA_COMMIT();
            load_kv(0, 0); CPA_COMMIT();
            CPA_WAIT1();
            __syncthreads();
        }

        uint32_t aq[8][4];
        {
            uint32_t qBase = sb + (uint32_t)(warp * 16) * FROWB + aOff;
#pragma unroll
            for (int kk = 0; kk < 8; kk++)
                ldsm4(aq[kk], qBase + (uint32_t)kk * 32);
        }

        float accO[16][4];
#pragma unroll
        for (int nt = 0; nt < 16; nt++)
#pragma unroll
            for (int r = 0; r < 4; r++) accO[nt][r] = 0.f;
        float m0 = -1e30f, m1 = -1e30f, l0 = 0.f, l1 = 0.f;

        for (int j = 0; j < 8; j++) {
            const int st = j & 1;
            CPA_WAIT0();
            __syncthreads();
            if (j + 1 < 8) { load_kv((j + 1) & 1, j + 1); CPA_COMMIT(); }

            const uint32_t kBase = sb + FTILE_B + (uint32_t)st * (2 * FTILE_B) + bOff;
            const uint32_t vBase = sb + FTILE_B + (uint32_t)st * (2 * FTILE_B) + FTILE_B + vOffT;

            float sA[16][4];
#pragma unroll
            for (int nt = 0; nt < 16; nt++)
#pragma unroll
                for (int r = 0; r < 4; r++) sA[nt][r] = 0.f;
#pragma unroll
            for (int kk = 0; kk < 8; kk++) {
#pragma unroll
                for (int np = 0; np < 8; np++) {
                    uint32_t bf[4];
                    ldsm4(bf, kBase + (uint32_t)(np * 16) * FROWB + (uint32_t)kk * 32);
                    mma16816(sA[2 * np],     aq[kk], bf[0], bf[1]);
                    mma16816(sA[2 * np + 1], aq[kk], bf[2], bf[3]);
                }
            }

            float mx0 = -1e30f, mx1 = -1e30f;
#pragma unroll
            for (int nt = 0; nt < 16; nt++) {
                mx0 = fmaxf(mx0, fmaxf(sA[nt][0], sA[nt][1]));
                mx1 = fmaxf(mx1, fmaxf(sA[nt][2], sA[nt][3]));
            }
            mx0 = fmaxf(mx0, __shfl_xor_sync(0xffffffffu, mx0, 1));
            mx0 = fmaxf(mx0, __shfl_xor_sync(0xffffffffu, mx0, 2));
            mx1 = fmaxf(mx1, __shfl_xor_sync(0xffffffffu, mx1, 1));
            mx1 = fmaxf(mx1, __shfl_xor_sync(0xffffffffu, mx1, 2));
            float mn0 = fmaxf(m0, mx0), mn1 = fmaxf(m1, mx1);
            float c0 = __expf(m0 - mn0), c1 = __expf(m1 - mn1);
            l0 *= c0; l1 *= c1;
#pragma unroll
            for (int nt = 0; nt < 16; nt++) {
                accO[nt][0] *= c0; accO[nt][1] *= c0;
                accO[nt][2] *= c1; accO[nt][3] *= c1;
            }
            float s0 = 0.f, s1 = 0.f;
            uint32_t pa0[16], pa1[16];
#pragma unroll
            for (int nt = 0; nt < 16; nt++) {
                float p0 = __expf(sA[nt][0] - mn0);
                float p1 = __expf(sA[nt][1] - mn0);
                float p2 = __expf(sA[nt][2] - mn1);
                float p3 = __expf(sA[nt][3] - mn1);
                s0 += p0 + p1; s1 += p2 + p3;
                pa0[nt] = packh2(p0, p1);
                pa1[nt] = packh2(p2, p3);
            }
            s0 += __shfl_xor_sync(0xffffffffu, s0, 1);
            s0 += __shfl_xor_sync(0xffffffffu, s0, 2);
            s1 += __shfl_xor_sync(0xffffffffu, s1, 1);
            s1 += __shfl_xor_sync(0xffffffffu, s1, 2);
            l0 += s0; l1 += s1; m0 = mn0; m1 = mn1;

#pragma unroll
            for (int kk = 0; kk < 8; kk++) {
                uint32_t a[4] = { pa0[2 * kk], pa1[2 * kk], pa0[2 * kk + 1], pa1[2 * kk + 1] };
#pragma unroll
                for (int np = 0; np < 8; np++) {
                    uint32_t bf[4];
                    ldsm4t(bf, vBase + (uint32_t)(kk * 16) * FROWB + (uint32_t)np * 32);
                    mma16816(accO[2 * np],     a, bf[0], bf[1]);
                    mma16816(accO[2 * np + 1], a, bf[2], bf[3]);
                }
            }
        }

        {
            float i0 = 1.f / l0, i1 = 1.f / l1;
            const int r = lane >> 2, cq = lane & 3;
            __half* Og = g_o + ((size_t)(b * LL + q0 + warp * 16)) * DIMM + h * HDIM;
#pragma unroll
            for (int nt = 0; nt < 16; nt++) {
                int col = nt * 8 + 2 * cq;
                *(__half2*)(Og + (size_t)r * DIMM + col) =
                    __floats2half2_rn(accO[nt][0] * i0, accO[nt][1] * i0);
                *(__half2*)(Og + (size_t)(r + 8) * DIMM + col) =
                    __floats2half2_rn(accO[nt][2] * i1, accO[nt][3] * i1);
            }
        }
    }
}

// ============================================================
// convert helpers
// ============================================================
__global__ void cvt_h_kernel(const float* __restrict__ s, __half* __restrict__ d, size_t n4)
{
    size_t i = (size_t)blockIdx.x * blockDim.x + threadIdx.x;
    if (i < n4) {
        float4 v = ((const float4*)s)[i];
        ((__half2*)d)[2 * i]     = __floats2half2_rn(v.x, v.y);
        ((__half2*)d)[2 * i + 1] = __floats2half2_rn(v.z, v.w);
    }
}

// merged weight transpose+convert: bx < nx1 -> (src1,dst1,N1), else (src2,dst2,N2)
__global__ void cvtT2_kernel(const float* __restrict__ src1, __half* __restrict__ dst1, int N1, int nx1,
                             const float* __restrict__ src2, __half* __restrict__ dst2, int N2,
                             int K)
{
    __shared__ float tile[32][33];
    int bx = blockIdx.x;
    const float* src; __half* dst; int N; int n0;
    if (bx < nx1) { src = src1; dst = dst1; N = N1; n0 = bx * 32; }
    else          { src = src2; dst = dst2; N = N2; n0 = (bx - nx1) * 32; }
    int k0 = blockIdx.y * 32;
    int tx = threadIdx.x, ty = threadIdx.y;
#pragma unroll
    for (int i = 0; i < 32; i += 8)
        tile[ty + i][tx] = src[(size_t)(k0 + ty + i) * N + n0 + tx];
    __syncthreads();
#pragma unroll
    for (int i = 0; i < 32; i += 8)
        dst[(size_t)(n0 + ty + i) * K + k0 + tx] = __float2half_rn(tile[tx][ty + i]);
}

// ============================================================
// RMSNorm + gain + RoPE -> half q (pre-scaled by SCALE), k
// shuffle-based reduction (2 barriers instead of 16)
// ============================================================
__global__ __launch_bounds__(256) void rmsrope_kernel(
    const float* __restrict__ cosb, const float* __restrict__ sinb,
    const float* __restrict__ gq, const float* __restrict__ gk)
{
    const int t = blockIdx.x;
    const int tid = threadIdx.x;
    const int warp = tid >> 5, lane = tid & 31;
    const __half2* baseq = (const __half2*)(g_qkvh + (size_t)t * QKVDIM);
    const __half2* basek = (const __half2*)(g_qkvh + (size_t)t * QKVDIM + DIMM);

    float sq = 0.f, sk = 0.f;
    for (int p = tid; p < DIMM / 2; p += 256) {
        float2 a = __half22float2(baseq[p]);
        float2 b = __half22float2(basek[p]);
        sq = fmaf(a.x, a.x, fmaf(a.y, a.y, sq));
        sk = fmaf(b.x, b.x, fmaf(b.y, b.y, sk));
    }
    // warp reduce
#pragma unroll
    for (int o = 16; o > 0; o >>= 1) {
        sq += __shfl_xor_sync(0xffffffffu, sq, o);
        sk += __shfl_xor_sync(0xffffffffu, sk, o);
    }
    __shared__ float wq_s[8], wk_s[8], bcast[2];
    if (lane == 0) { wq_s[warp] = sq; wk_s[warp] = sk; }
    __syncthreads();
    if (warp == 0) {
        float a = (lane < 8) ? wq_s[lane] : 0.f;
        float b = (lane < 8) ? wk_s[lane] : 0.f;
#pragma unroll
        for (int o = 4; o > 0; o >>= 1) {
            a += __shfl_xor_sync(0xffffffffu, a, o);
            b += __shfl_xor_sync(0xffffffffu, b, o);
        }
        if (lane == 0) {
            bcast[0] = rsqrtf(a / (float)DIMM + EPS);
            bcast[1] = rsqrtf(b / (float)DIMM + EPS);
        }
    }
    __syncthreads();
    const float rq = bcast[0], rk = bcast[1];

    const int l = t & (LL - 1);
    const float* cl = cosb + (size_t)l * HDIM;
    const float* sl = sinb + (size_t)l * HDIM;
    __half* qo = g_q + (size_t)t * DIMM;
    __half* ko = g_k + (size_t)t * DIMM;

    for (int p = tid; p < DIMM / 2; p += 256) {
        int d = 2 * p;
        int hd = d & (HDIM - 1);
        float c = cl[hd];
        float s = sl[hd + 1];
        float2 gv = *(const float2*)(gq + d);
        float2 kv = *(const float2*)(gk + d);
        float2 av = __half22float2(baseq[p]);
        float2 bv = __half22float2(basek[p]);
        float x0 = av.x * rq * gv.x;
        float x1 = av.y * rq * gv.y;
        *(__half2*)(qo + d) = __floats2half2_rn((x0 * c - x1 * s) * SCALE,
                                                (x0 * s + x1 * c) * SCALE);
        float y0 = bv.x * rk * kv.x;
        float y1 = bv.y * rk * kv.y;
        *(__half2*)(ko + d) = __floats2half2_rn(y0 * c - y1 * s, y0 * s + y1 * c);
    }
}

// ============================================================
// launch
// ============================================================
extern "C" void kernel_launch(void* const* d_in, const int* in_sizes, int n_in,
                              void* d_out, int out_size)
{
    const float* x     = (const float*)d_in[0];
    const float* cosb  = (const float*)d_in[1];
    const float* sinb  = (const float*)d_in[2];
    const float* Wqkv  = (const float*)d_in[3];
    const float* bqkv  = (const float*)d_in[4];
    const float* gq    = (const float*)d_in[5];
    const float* gk    = (const float*)d_in[6];
    const float* Wout  = (const float*)d_in[7];
    const float* bout  = (const float*)d_in[8];
    float* out = (float*)d_out;

    void* p_qkvh; cudaGetSymbolAddress(&p_qkvh, g_qkvh);
    void* p_o;    cudaGetSymbolAddress(&p_o,    g_o);
    void* p_wq;   cudaGetSymbolAddress(&p_wq,   g_wq);
    void* p_wo;   cudaGetSymbolAddress(&p_wo,   g_wo);
    void* p_x;    cudaGetSymbolAddress(&p_x,    g_x);

    cudaFuncSetAttribute(tc_gemm, cudaFuncAttributeMaxDynamicSharedMemorySize, GEMM_SMEM);
    cudaFuncSetAttribute(flash_kernel, cudaFuncAttributeMaxDynamicSharedMemorySize, FLASH_SMEM);

    // 0) merged weight transpose + fp16 rounding; activation rounding
    cvtT2_kernel<<<dim3(QKVDIM / 32 + DIMM / 32, DIMM / 32), dim3(32, 8)>>>(
        Wqkv, (__half*)p_wq, QKVDIM, QKVDIM / 32,
        Wout, (__half*)p_wo, DIMM, DIMM);
    {
        size_t n4 = (size_t)TOKENS * DIMM / 4;
        cvt_h_kernel<<<(unsigned)((n4 + 255) / 256), 256>>>(x, (__half*)p_x, n4);
    }

    // 1) QKV projection -> half directly
    tc_gemm<<<dim3(TOKENS / 128, QKVDIM / 128, 1), 256, GEMM_SMEM>>>(
        (const __half*)p_x, (const __half*)p_wq, bqkv, p_qkvh,
        DIMM, DIMM, QKVDIM, DIMM, 1.f, 1);

    // 2) RMSNorm + RoPE (half in/out, q pre-scaled)
    rmsrope_kernel<<<TOKENS, 256>>>(cosb, sinb, gq, gk);

    // 3) fused attention: persistent; V read straight from g_qkvh (trans-ldsm)
    flash_kernel<<<FLASH_GRID, 256, FLASH_SMEM>>>();

    // 4) out projection (f32 out to d_out)
    tc_gemm<<<dim3(TOKENS / 128, DIMM / 128, 1), 256, GEMM_SMEM>>>(
        (const __half*)p_o, (const __half*)p_wo, bout, out,
        DIMM, DIMM, DIMM, DIMM, 1.f, 0);
}

// round 16
// speedup vs baseline: 1.1777x; 1.0014x over previous
#include <cuda_runtime.h>
#include <cuda_fp16.h>
#include <math.h>
#include <stdint.h>

// Problem constants
#define DIMM 5120
#define NHEADS 40
#define HDIM 128
#define BB 2
#define LL 1024
#define TOKENS (BB*LL)          // 2048
#define QKVDIM (3*DIMM)         // 15360
#define SCALE 0.08838834764831845f
#define EPS 1e-6f

// -------- scratch (static device globals; no runtime allocation) --------
__device__ __half g_qkvh[(size_t)TOKENS * QKVDIM];          // 62.9 MB half
__device__ __half g_q[(size_t)TOKENS * DIMM];               // scaled by SCALE
__device__ __half g_k[(size_t)TOKENS * DIMM];
__device__ __half g_o[(size_t)TOKENS * DIMM];
__device__ __half g_wq[(size_t)QKVDIM * DIMM];              // W_qkv^T [N,K]
__device__ __half g_wo[(size_t)DIMM * DIMM];                // W_out^T [N,K]
__device__ __half g_x[(size_t)TOKENS * DIMM];               // x, half

// ============================================================
// helpers
// ============================================================
__device__ __forceinline__ uint32_t smem_u32(const void* p) {
    uint32_t a;
    asm("{ .reg .u64 t; cvta.to.shared.u64 t, %1; cvt.u32.u64 %0, t; }" : "=r"(a) : "l"(p));
    return a;
}
__device__ __forceinline__ void cpa16(uint32_t dst, const void* src) {
    asm volatile("cp.async.cg.shared.global [%0], [%1], 16;" :: "r"(dst), "l"(src));
}
#define CPA_COMMIT() asm volatile("cp.async.commit_group;" ::: "memory")
#define CPA_WAIT1()  asm volatile("cp.async.wait_group 1;" ::: "memory")
#define CPA_WAIT0()  asm volatile("cp.async.wait_group 0;" ::: "memory")

// fp16 m16n8k16, f32 accum
__device__ __forceinline__ void mma16816(float* d, const uint32_t* a, uint32_t b0, uint32_t b1) {
    asm volatile(
        "mma.sync.aligned.m16n8k16.row.col.f32.f16.f16.f32 "
        "{%0,%1,%2,%3}, {%4,%5,%6,%7}, {%8,%9}, {%0,%1,%2,%3};"
        : "+f"(d[0]), "+f"(d[1]), "+f"(d[2]), "+f"(d[3])
        : "r"(a[0]), "r"(a[1]), "r"(a[2]), "r"(a[3]), "r"(b0), "r"(b1));
}
__device__ __forceinline__ void ldsm4(uint32_t* r, uint32_t addr) {
    asm volatile("ldmatrix.sync.aligned.m8n8.x4.shared.b16 {%0,%1,%2,%3}, [%4];"
        : "=r"(r[0]), "=r"(r[1]), "=r"(r[2]), "=r"(r[3]) : "r"(addr));
}
__device__ __forceinline__ void ldsm4t(uint32_t* r, uint32_t addr) {
    asm volatile("ldmatrix.sync.aligned.m8n8.x4.trans.shared.b16 {%0,%1,%2,%3}, [%4];"
        : "=r"(r[0]), "=r"(r[1]), "=r"(r[2]), "=r"(r[3]) : "r"(addr));
}
__device__ __forceinline__ uint32_t packh2(float x, float y) {
    __half2 h = __floats2half2_rn(x, y);
    return *(uint32_t*)&h;
}

// ============================================================
// shared GEMM config
// ============================================================
#define KC 64
#define ROWB 144
#define TILE_B (128 * ROWB)
#define STAGE_B (2 * TILE_B)
#define NSTG 3
#define GEMM_SMEM (NSTG * STAGE_B)          // 110592 B
#define GEMM_GRID 296

// ============================================================
// fp16 mma.sync GEMM (non-persistent; used for QKV, 6.5 waves)
// CTA tile 128x128, 256 threads, 8 warps 2(M)x4(N), warp tile 64x32.
// ============================================================
__global__ __launch_bounds__(256) void tc_gemm(
    const __half* __restrict__ A, const __half* __restrict__ Bt,
    const float* __restrict__ bias, void* __restrict__ Cv,
    int lda, int ldb, int ldc, int K, float alpha, int store_half)
{
    extern __shared__ char sm[];
    const uint32_t sb = smem_u32(sm);

    const int tid  = threadIdx.x;
    const int warp = tid >> 5;
    const int lane = tid & 31;
    const int wm = warp >> 2;
    const int wn = warp & 3;
    const int m0 = blockIdx.x * 128;
    const int n0 = blockIdx.y * 128;

    const uint32_t aOff = (uint32_t)(lane & 15) * ROWB + (uint32_t)(lane >> 4) * 16;
    const uint32_t bOff = (uint32_t)((lane & 7) + ((lane >> 4) & 1) * 8) * ROWB
                        + (uint32_t)((lane >> 3) & 1) * 16;

    float acc[4][4][4];
#pragma unroll
    for (int mt = 0; mt < 4; mt++)
#pragma unroll
        for (int nt = 0; nt < 4; nt++)
#pragma unroll
            for (int r = 0; r < 4; r++) acc[mt][nt][r] = 0.f;

    const int nch = K / KC;

    auto load_chunk = [&](int st, int kc) {
        uint32_t base = sb + (uint32_t)st * STAGE_B;
#pragma unroll
        for (int i = 0; i < 4; i++) {
            int op = tid + i * 256;
            int row = op >> 3, g = op & 7;
            uint32_t off = (uint32_t)row * ROWB + (uint32_t)g * 16;
            cpa16(base + off,
                  (const char*)A + ((size_t)(m0 + row) * lda + kc + g * 8) * 2);
            cpa16(base + TILE_B + off,
                  (const char*)Bt + ((size_t)(n0 + row) * ldb + kc + g * 8) * 2);
        }
    };

    load_chunk(0, 0);       CPA_COMMIT();
    if (nch > 1) { load_chunk(1, KC); CPA_COMMIT(); }

    for (int c = 0; c < nch; c++) {
        const int st = c % NSTG;
        if (c + 1 < nch) { CPA_WAIT1(); } else { CPA_WAIT0(); }
        __syncthreads();
        if (c + 2 < nch) { load_chunk((c + 2) % NSTG, (c + 2) * KC); CPA_COMMIT(); }

        const uint32_t aBase = sb + (uint32_t)st * STAGE_B
                             + (uint32_t)(wm * 64) * ROWB + aOff;
        const uint32_t bBase = sb + (uint32_t)st * STAGE_B + TILE_B
                             + (uint32_t)(wn * 32) * ROWB + bOff;

#pragma unroll
        for (int s = 0; s < 4; s++) {
            const uint32_t kb = (uint32_t)s * 32;
            uint32_t af[4][4];
#pragma unroll
            for (int mt = 0; mt < 4; mt++)
                ldsm4(af[mt], aBase + (uint32_t)(mt * 16) * ROWB + kb);
            uint32_t bf[2][4];
#pragma unroll
            for (int np = 0; np < 2; np++)
                ldsm4(bf[np], bBase + (uint32_t)(np * 16) * ROWB + kb);
#pragma unroll
            for (int mt = 0; mt < 4; mt++)
#pragma unroll
                for (int nt = 0; nt < 4; nt++)
                    mma16816(acc[mt][nt], af[mt],
                             bf[nt >> 1][(nt & 1) * 2], bf[nt >> 1][(nt & 1) * 2 + 1]);
        }
    }

    {
        const int r = lane >> 2, cq = lane & 3;
#pragma unroll
        for (int mt = 0; mt < 4; mt++) {
            int row = m0 + wm * 64 + mt * 16 + r;
#pragma unroll
            for (int nt = 0; nt < 4; nt++) {
                int col = n0 + wn * 32 + nt * 8 + 2 * cq;
                float bvx = 0.f, bvy = 0.f;
                if (bias) { float2 bv = *(const float2*)(bias + col); bvx = bv.x; bvy = bv.y; }
                float o0x = fmaf(acc[mt][nt][0], alpha, bvx);
                float o0y = fmaf(acc[mt][nt][1], alpha, bvy);
                float o1x = fmaf(acc[mt][nt][2], alpha, bvx);
                float o1y = fmaf(acc[mt][nt][3], alpha, bvy);
                if (store_half) {
                    __half* C = (__half*)Cv;
                    *(__half2*)(C + (size_t)row * ldc + col) = __floats2half2_rn(o0x, o0y);
                    *(__half2*)(C + (size_t)(row + 8) * ldc + col) = __floats2half2_rn(o1x, o1y);
                } else {
                    float* C = (float*)Cv;
                    *(float2*)(C + (size_t)row * ldc + col) = make_float2(o0x, o0y);
                    *(float2*)(C + (size_t)(row + 8) * ldc + col) = make_float2(o1x, o1y);
                }
            }
        }
    }
}

// ============================================================
// PERSISTENT variant (used for out-proj: 640 tiles / 2.16 waves
// -> tail-free). Same mainloop; 296 CTAs loop over tiles.
// ============================================================
__global__ __launch_bounds__(256, 2) void tc_gemm_p(
    const __half* __restrict__ A, const __half* __restrict__ Bt,
    const float* __restrict__ bias, void* __restrict__ Cv,
    int lda, int ldb, int ldc, int K, float alpha, int store_half,
    int mtiles, int ntot)
{
    extern __shared__ char sm[];
    const uint32_t sb = smem_u32(sm);

    const int tid  = threadIdx.x;
    const int warp = tid >> 5;
    const int lane = tid & 31;
    const int wm = warp >> 2;
    const int wn = warp & 3;

    const uint32_t aOff = (uint32_t)(lane & 15) * ROWB + (uint32_t)(lane >> 4) * 16;
    const uint32_t bOff = (uint32_t)((lane & 7) + ((lane >> 4) & 1) * 8) * ROWB
                        + (uint32_t)((lane >> 3) & 1) * 16;

    const int nch = K / KC;

    for (int t = blockIdx.x; t < ntot; t += gridDim.x) {
        const int m0 = (t % mtiles) * 128;
        const int n0 = (t / mtiles) * 128;

        float acc[4][4][4];
#pragma unroll
        for (int mt = 0; mt < 4; mt++)
#pragma unroll
            for (int nt = 0; nt < 4; nt++)
#pragma unroll
                for (int r = 0; r < 4; r++) acc[mt][nt][r] = 0.f;

        auto load_chunk = [&](int st, int kc) {
            uint32_t base = sb + (uint32_t)st * STAGE_B;
#pragma unroll
            for (int i = 0; i < 4; i++) {
                int op = tid + i * 256;
                int row = op >> 3, g = op & 7;
                uint32_t off = (uint32_t)row * ROWB + (uint32_t)g * 16;
                cpa16(base + off,
                      (const char*)A + ((size_t)(m0 + row) * lda + kc + g * 8) * 2);
                cpa16(base + TILE_B + off,
                      (const char*)Bt + ((size_t)(n0 + row) * ldb + kc + g * 8) * 2);
            }
        };

        load_chunk(0, 0);       CPA_COMMIT();
        if (nch > 1) { load_chunk(1, KC); CPA_COMMIT(); }

        for (int c = 0; c < nch; c++) {
            const int st = c % NSTG;
            if (c + 1 < nch) { CPA_WAIT1(); } else { CPA_WAIT0(); }
            __syncthreads();
            if (c + 2 < nch) { load_chunk((c + 2) % NSTG, (c + 2) * KC); CPA_COMMIT(); }

            const uint32_t aBase = sb + (uint32_t)st * STAGE_B
                                 + (uint32_t)(wm * 64) * ROWB + aOff;
            const uint32_t bBase = sb + (uint32_t)st * STAGE_B + TILE_B
                                 + (uint32_t)(wn * 32) * ROWB + bOff;

#pragma unroll
            for (int s = 0; s < 4; s++) {
                const uint32_t kb = (uint32_t)s * 32;
                uint32_t af[4][4];
#pragma unroll
                for (int mt = 0; mt < 4; mt++)
                    ldsm4(af[mt], aBase + (uint32_t)(mt * 16) * ROWB + kb);
                uint32_t bf[2][4];
#pragma unroll
                for (int np = 0; np < 2; np++)
                    ldsm4(bf[np], bBase + (uint32_t)(np * 16) * ROWB + kb);
#pragma unroll
                for (int mt = 0; mt < 4; mt++)
#pragma unroll
                    for (int nt = 0; nt < 4; nt++)
                        mma16816(acc[mt][nt], af[mt],
                                 bf[nt >> 1][(nt & 1) * 2], bf[nt >> 1][(nt & 1) * 2 + 1]);
            }
        }

        {
            const int r = lane >> 2, cq = lane & 3;
#pragma unroll
            for (int mt = 0; mt < 4; mt++) {
                int row = m0 + wm * 64 + mt * 16 + r;
#pragma unroll
                for (int nt = 0; nt < 4; nt++) {
                    int col = n0 + wn * 32 + nt * 8 + 2 * cq;
                    float bvx = 0.f, bvy = 0.f;
                    if (bias) { float2 bv = *(const float2*)(bias + col); bvx = bv.x; bvy = bv.y; }
                    float o0x = fmaf(acc[mt][nt][0], alpha, bvx);
                    float o0y = fmaf(acc[mt][nt][1], alpha, bvy);
                    float o1x = fmaf(acc[mt][nt][2], alpha, bvx);
                    float o1y = fmaf(acc[mt][nt][3], alpha, bvy);
                    if (store_half) {
                        __half* C = (__half*)Cv;
                        *(__half2*)(C + (size_t)row * ldc + col) = __floats2half2_rn(o0x, o0y);
                        *(__half2*)(C + (size_t)(row + 8) * ldc + col) = __floats2half2_rn(o1x, o1y);
                    } else {
                        float* C = (float*)Cv;
                        *(float2*)(C + (size_t)row * ldc + col) = make_float2(o0x, o0y);
                        *(float2*)(C + (size_t)(row + 8) * ldc + col) = make_float2(o1x, o1y);
                    }
                }
            }
        }
        __syncthreads();   // protect smem stages before next tile's prologue
    }
}

// ============================================================
// Persistent flash attention: work item = (q-tile, bh).
// V loaded directly from g_qkvh [seq][d] via ldmatrix.trans.
// ============================================================
#define FROWB 272
#define FTILE_B (128 * FROWB)               // 34816
#define FLASH_SMEM (5 * FTILE_B)            // 174080: Q + 2x(K+V)
#define FLASH_GRID 148
#define FLASH_ITEMS (BB * NHEADS * (LL / 128))   // 640

__global__ __launch_bounds__(256, 1) void flash_kernel()
{
    extern __shared__ char sm[];
    const uint32_t sb = smem_u32(sm);
    const int tid = threadIdx.x, warp = tid >> 5, lane = tid & 31;

    const uint32_t aOff = (uint32_t)(lane & 15) * FROWB + (uint32_t)(lane >> 4) * 16;
    const uint32_t bOff = (uint32_t)((lane & 7) + ((lane >> 4) & 1) * 8) * FROWB
                        + (uint32_t)((lane >> 3) & 1) * 16;
    const uint32_t vOffT = (uint32_t)((lane & 7) + ((lane >> 3) & 1) * 8) * FROWB
                         + (uint32_t)(lane >> 4) * 16;

    for (int it = blockIdx.x; it < FLASH_ITEMS; it += gridDim.x) {
        const int q0 = (it & 7) * 128;
        const int bh = it >> 3;
        const int b = bh / NHEADS, h = bh % NHEADS;

        const char* Qg = (const char*)(g_q + ((size_t)(b * LL + q0)) * DIMM + h * HDIM);
        const char* Kg = (const char*)(g_k + ((size_t)(b * LL)) * DIMM + h * HDIM);
        const char* Vg = (const char*)(g_qkvh + (size_t)(b * LL) * QKVDIM + 2 * DIMM + h * HDIM);

        auto load_kv = [&](int st, int j) {
            uint32_t kb = sb + FTILE_B + (uint32_t)st * (2 * FTILE_B);
            uint32_t vb = kb + FTILE_B;
#pragma unroll
            for (int i = 0; i < 8; i++) {
                int op = tid + i * 256;
                int row = op >> 4, g = op & 15;
                uint32_t off = (uint32_t)row * FROWB + (uint32_t)g * 16;
                cpa16(kb + off, Kg + ((size_t)(j * 128 + row) * DIMM) * 2 + g * 16);
                cpa16(vb + off, Vg + ((size_t)(j * 128 + row) * QKVDIM) * 2 + g * 16);
            }
        };

        {
#pragma unroll
            for (int i = 0; i < 8; i++) {
                int op = tid + i * 256;
                int row = op >> 4, g = op & 15;
                cpa16(sb + (uint32_t)row * FROWB + (uint32_t)g * 16,
                      Qg + (size_t)row * DIMM * 2 + g * 16);
            }
            CPA_COMMIT();
            load_kv(0, 0); CPA_COMMIT();
            CPA_WAIT1();
            __syncthreads();
        }

        uint32_t aq[8][4];
        {
            uint32_t qBase = sb + (uint32_t)(warp * 16) * FROWB + aOff;
#pragma unroll
            for (int kk = 0; kk < 8; kk++)
                ldsm4(aq[kk], qBase + (uint32_t)kk * 32);
        }

        float accO[16][4];
#pragma unroll
        for (int nt = 0; nt < 16; nt++)
#pragma unroll
            for (int r = 0; r < 4; r++) accO[nt][r] = 0.f;
        float m0 = -1e30f, m1 = -1e30f, l0 = 0.f, l1 = 0.f;

        for (int j = 0; j < 8; j++) {
            const int st = j & 1;
            CPA_WAIT0();
            __syncthreads();
            if (j + 1 < 8) { load_kv((j + 1) & 1, j + 1); CPA_COMMIT(); }

            const uint32_t kBase = sb + FTILE_B + (uint32_t)st * (2 * FTILE_B) + bOff;
            const uint32_t vBase = sb + FTILE_B + (uint32_t)st * (2 * FTILE_B) + FTILE_B + vOffT;

            float sA[16][4];
#pragma unroll
            for (int nt = 0; nt < 16; nt++)
#pragma unroll
                for (int r = 0; r < 4; r++) sA[nt][r] = 0.f;
#pragma unroll
            for (int kk = 0; kk < 8; kk++) {
#pragma unroll
                for (int np = 0; np < 8; np++) {
                    uint32_t bf[4];
                    ldsm4(bf, kBase + (uint32_t)(np * 16) * FROWB + (uint32_t)kk * 32);
                    mma16816(sA[2 * np],     aq[kk], bf[0], bf[1]);
                    mma16816(sA[2 * np + 1], aq[kk], bf[2], bf[3]);
                }
            }

            float mx0 = -1e30f, mx1 = -1e30f;
#pragma unroll
            for (int nt = 0; nt < 16; nt++) {
                mx0 = fmaxf(mx0, fmaxf(sA[nt][0], sA[nt][1]));
                mx1 = fmaxf(mx1, fmaxf(sA[nt][2], sA[nt][3]));
            }
            mx0 = fmaxf(mx0, __shfl_xor_sync(0xffffffffu, mx0, 1));
            mx0 = fmaxf(mx0, __shfl_xor_sync(0xffffffffu, mx0, 2));
            mx1 = fmaxf(mx1, __shfl_xor_sync(0xffffffffu, mx1, 1));
            mx1 = fmaxf(mx1, __shfl_xor_sync(0xffffffffu, mx1, 2));
            float mn0 = fmaxf(m0, mx0), mn1 = fmaxf(m1, mx1);
            float c0 = __expf(m0 - mn0), c1 = __expf(m1 - mn1);
            l0 *= c0; l1 *= c1;
#pragma unroll
            for (int nt = 0; nt < 16; nt++) {
                accO[nt][0] *= c0; accO[nt][1] *= c0;
                accO[nt][2] *= c1; accO[nt][3] *= c1;
            }
            float s0 = 0.f, s1 = 0.f;
            uint32_t pa0[16], pa1[16];
#pragma unroll
            for (int nt = 0; nt < 16; nt++) {
                float p0 = __expf(sA[nt][0] - mn0);
                float p1 = __expf(sA[nt][1] - mn0);
                float p2 = __expf(sA[nt][2] - mn1);
                float p3 = __expf(sA[nt][3] - mn1);
                s0 += p0 + p1; s1 += p2 + p3;
                pa0[nt] = packh2(p0, p1);
                pa1[nt] = packh2(p2, p3);
            }
            s0 += __shfl_xor_sync(0xffffffffu, s0, 1);
            s0 += __shfl_xor_sync(0xffffffffu, s0, 2);
            s1 += __shfl_xor_sync(0xffffffffu, s1, 1);
            s1 += __shfl_xor_sync(0xffffffffu, s1, 2);
            l0 += s0; l1 += s1; m0 = mn0; m1 = mn1;

#pragma unroll
            for (int kk = 0; kk < 8; kk++) {
                uint32_t a[4] = { pa0[2 * kk], pa1[2 * kk], pa0[2 * kk + 1], pa1[2 * kk + 1] };
#pragma unroll
                for (int np = 0; np < 8; np++) {
                    uint32_t bf[4];
                    ldsm4t(bf, vBase + (uint32_t)(kk * 16) * FROWB + (uint32_t)np * 32);
                    mma16816(accO[2 * np],     a, bf[0], bf[1]);
                    mma16816(accO[2 * np + 1], a, bf[2], bf[3]);
                }
            }
        }

        {
            float i0 = 1.f / l0, i1 = 1.f / l1;
            const int r = lane >> 2, cq = lane & 3;
            __half* Og = g_o + ((size_t)(b * LL + q0 + warp * 16)) * DIMM + h * HDIM;
#pragma unroll
            for (int nt = 0; nt < 16; nt++) {
                int col = nt * 8 + 2 * cq;
                *(__half2*)(Og + (size_t)r * DIMM + col) =
                    __floats2half2_rn(accO[nt][0] * i0, accO[nt][1] * i0);
                *(__half2*)(Og + (size_t)(r + 8) * DIMM + col) =
                    __floats2half2_rn(accO[nt][2] * i1, accO[nt][3] * i1);
            }
        }
    }
}

// ============================================================
// convert helpers
// ============================================================
__global__ void cvt_h_kernel(const float* __restrict__ s, __half* __restrict__ d, size_t n4)
{
    size_t i = (size_t)blockIdx.x * blockDim.x + threadIdx.x;
    if (i < n4) {
        float4 v = ((const float4*)s)[i];
        ((__half2*)d)[2 * i]     = __floats2half2_rn(v.x, v.y);
        ((__half2*)d)[2 * i + 1] = __floats2half2_rn(v.z, v.w);
    }
}

// merged weight transpose+convert
__global__ void cvtT2_kernel(const float* __restrict__ src1, __half* __restrict__ dst1, int N1, int nx1,
                             const float* __restrict__ src2, __half* __restrict__ dst2, int N2,
                             int K)
{
    __shared__ float tile[32][33];
    int bx = blockIdx.x;
    const float* src; __half* dst; int N; int n0;
    if (bx < nx1) { src = src1; dst = dst1; N = N1; n0 = bx * 32; }
    else          { src = src2; dst = dst2; N = N2; n0 = (bx - nx1) * 32; }
    int k0 = blockIdx.y * 32;
    int tx = threadIdx.x, ty = threadIdx.y;
#pragma unroll
    for (int i = 0; i < 32; i += 8)
        tile[ty + i][tx] = src[(size_t)(k0 + ty + i) * N + n0 + tx];
    __syncthreads();
#pragma unroll
    for (int i = 0; i < 32; i += 8)
        dst[(size_t)(n0 + ty + i) * K + k0 + tx] = __float2half_rn(tile[tx][ty + i]);
}

// ============================================================
// RMSNorm + gain + RoPE -> half q (pre-scaled by SCALE), k
// ============================================================
__global__ __launch_bounds__(256) void rmsrope_kernel(
    const float* __restrict__ cosb, const float* __restrict__ sinb,
    const float* __restrict__ gq, const float* __restrict__ gk)
{
    const int t = blockIdx.x;
    const int tid = threadIdx.x;
    const int warp = tid >> 5, lane = tid & 31;
    const __half2* baseq = (const __half2*)(g_qkvh + (size_t)t * QKVDIM);
    const __half2* basek = (const __half2*)(g_qkvh + (size_t)t * QKVDIM + DIMM);

    float sq = 0.f, sk = 0.f;
    for (int p = tid; p < DIMM / 2; p += 256) {
        float2 a = __half22float2(baseq[p]);
        float2 b = __half22float2(basek[p]);
        sq = fmaf(a.x, a.x, fmaf(a.y, a.y, sq));
        sk = fmaf(b.x, b.x, fmaf(b.y, b.y, sk));
    }
#pragma unroll
    for (int o = 16; o > 0; o >>= 1) {
        sq += __shfl_xor_sync(0xffffffffu, sq, o);
        sk += __shfl_xor_sync(0xffffffffu, sk, o);
    }
    __shared__ float wq_s[8], wk_s[8], bcast[2];
    if (lane == 0) { wq_s[warp] = sq; wk_s[warp] = sk; }
    __syncthreads();
    if (warp == 0) {
        float a = (lane < 8) ? wq_s[lane] : 0.f;
        float b = (lane < 8) ? wk_s[lane] : 0.f;
#pragma unroll
        for (int o = 4; o > 0; o >>= 1) {
            a += __shfl_xor_sync(0xffffffffu, a, o);
            b += __shfl_xor_sync(0xffffffffu, b, o);
        }
        if (lane == 0) {
            bcast[0] = rsqrtf(a / (float)DIMM + EPS);
            bcast[1] = rsqrtf(b / (float)DIMM + EPS);
        }
    }
    __syncthreads();
    const float rq = bcast[0], rk = bcast[1];

    const int l = t & (LL - 1);
    const float* cl = cosb + (size_t)l * HDIM;
    const float* sl = sinb + (size_t)l * HDIM;
    __half* qo = g_q + (size_t)t * DIMM;
    __half* ko = g_k + (size_t)t * DIMM;

    for (int p = tid; p < DIMM / 2; p += 256) {
        int d = 2 * p;
        int hd = d & (HDIM - 1);
        float c = cl[hd];
        float s = sl[hd + 1];
        float2 gv = *(const float2*)(gq + d);
        float2 kv = *(const float2*)(gk + d);
        float2 av = __half22float2(baseq[p]);
        float2 bv = __half22float2(basek[p]);
        float x0 = av.x * rq * gv.x;
        float x1 = av.y * rq * gv.y;
        *(__half2*)(qo + d) = __floats2half2_rn((x0 * c - x1 * s) * SCALE,
                                                (x0 * s + x1 * c) * SCALE);
        float y0 = bv.x * rk * kv.x;
        float y1 = bv.y * rk * kv.y;
        *(__half2*)(ko + d) = __floats2half2_rn(y0 * c - y1 * s, y0 * s + y1 * c);
    }
}

// ============================================================
// launch
// ============================================================
extern "C" void kernel_launch(void* const* d_in, const int* in_sizes, int n_in,
                              void* d_out, int out_size)
{
    const float* x     = (const float*)d_in[0];
    const float* cosb  = (const float*)d_in[1];
    const float* sinb  = (const float*)d_in[2];
    const float* Wqkv  = (const float*)d_in[3];
    const float* bqkv  = (const float*)d_in[4];
    const float* gq    = (const float*)d_in[5];
    const float* gk    = (const float*)d_in[6];
    const float* Wout  = (const float*)d_in[7];
    const float* bout  = (const float*)d_in[8];
    float* out = (float*)d_out;

    void* p_qkvh; cudaGetSymbolAddress(&p_qkvh, g_qkvh);
    void* p_o;    cudaGetSymbolAddress(&p_o,    g_o);
    void* p_wq;   cudaGetSymbolAddress(&p_wq,   g_wq);
    void* p_wo;   cudaGetSymbolAddress(&p_wo,   g_wo);
    void* p_x;    cudaGetSymbolAddress(&p_x,    g_x);

    cudaFuncSetAttribute(tc_gemm,   cudaFuncAttributeMaxDynamicSharedMemorySize, GEMM_SMEM);
    cudaFuncSetAttribute(tc_gemm_p, cudaFuncAttributeMaxDynamicSharedMemorySize, GEMM_SMEM);
    cudaFuncSetAttribute(flash_kernel, cudaFuncAttributeMaxDynamicSharedMemorySize, FLASH_SMEM);

    // 0) merged weight transpose + fp16 rounding; activation rounding
    cvtT2_kernel<<<dim3(QKVDIM / 32 + DIMM / 32, DIMM / 32), dim3(32, 8)>>>(
        Wqkv, (__half*)p_wq, QKVDIM, QKVDIM / 32,
        Wout, (__half*)p_wo, DIMM, DIMM);
    {
        size_t n4 = (size_t)TOKENS * DIMM / 4;
        cvt_h_kernel<<<(unsigned)((n4 + 255) / 256), 256>>>(x, (__half*)p_x, n4);
    }

    // 1) QKV projection -> half directly (non-persistent: 6.5 waves)
    tc_gemm<<<dim3(TOKENS / 128, QKVDIM / 128, 1), 256, GEMM_SMEM>>>(
        (const __half*)p_x, (const __half*)p_wq, bqkv, p_qkvh,
        DIMM, DIMM, QKVDIM, DIMM, 1.f, 1);

    // 2) RMSNorm + RoPE (half in/out, q pre-scaled)
    rmsrope_kernel<<<TOKENS, 256>>>(cosb, sinb, gq, gk);

    // 3) fused attention: persistent; V read straight from g_qkvh
    flash_kernel<<<FLASH_GRID, 256, FLASH_SMEM>>>();

    // 4) out projection (PERSISTENT: 640 tiles = 2.16 waves -> tail-free)
    tc_gemm_p<<<GEMM_GRID, 256, GEMM_SMEM>>>(
        (const __half*)p_o, (const __half*)p_wo, bout, out,
        DIMM, DIMM, DIMM, DIMM, 1.f, 0,
        TOKENS / 128, (TOKENS / 128) * (DIMM / 128));
}